// round 2
// baseline (speedup 1.0000x reference)
#include <cuda_runtime.h>
#include <math.h>

#define HIDDEN      128
#define INPUT_SZ    64
#define NUM_ACT     16
#define BATCH_N     65536
#define TPB         128

__device__ __forceinline__ float fsig(float x) {
    // 1/(1+e^-x); __expf ~2ulp, __fdividef ~2ulp -> plenty for 1e-3
    return __fdividef(1.0f, 1.0f + __expf(-x));
}

__device__ __forceinline__ float ftanh(float x) {
    // tanh via exp on |x| to avoid overflow -> NaN for large negative x
    float ax = fabsf(x);
    float e  = __expf(-2.0f * ax);
    float t  = __fdividef(1.0f - e, 1.0f + e);
    return copysignf(t, x);
}

extern "C" __global__ void __launch_bounds__(TPB, 3)
lstm_policy_kernel(const float* __restrict__ x,
                   const float* __restrict__ Wih0,
                   const float* __restrict__ bih0,
                   const float* __restrict__ bhh0,
                   const float* __restrict__ Wih1,
                   const float* __restrict__ bih1,
                   const float* __restrict__ bhh1,
                   const float* __restrict__ Wp,
                   const float* __restrict__ bp,
                   const float* __restrict__ Wv,
                   const float* __restrict__ bv,
                   float* __restrict__ out_policy,
                   float* __restrict__ out_value)
{
    // h0 tile, k-major: hs[j*TPB + t]. Each thread reads/writes only its own
    // column t -> conflict-free (consecutive lanes -> consecutive banks) and
    // no __syncthreads needed anywhere.
    extern __shared__ float hs[];

    const int t = threadIdx.x;
    const int e = blockIdx.x * TPB + t;   // grid is exactly BATCH_N/TPB

    // ---- load x row into registers (16 x LDG.128) ----
    float xr[INPUT_SZ];
    {
        const float4* xp = reinterpret_cast<const float4*>(x + (size_t)e * INPUT_SZ);
#pragma unroll
        for (int k = 0; k < INPUT_SZ / 4; k++) {
            float4 v = __ldg(xp + k);
            xr[4*k+0] = v.x; xr[4*k+1] = v.y; xr[4*k+2] = v.z; xr[4*k+3] = v.w;
        }
    }

    // ---- layer 0: h0 = sig(o) * tanh( sig(i) * tanh(g) )   (c=0 => f-gate dead) ----
    {
        const float4* W0 = reinterpret_cast<const float4*>(Wih0);
#pragma unroll 1
        for (int j = 0; j < HIDDEN; j++) {
            float ai = __ldg(bih0 + j)            + __ldg(bhh0 + j);
            float ag = __ldg(bih0 + 2*HIDDEN + j) + __ldg(bhh0 + 2*HIDDEN + j);
            float ao = __ldg(bih0 + 3*HIDDEN + j) + __ldg(bhh0 + 3*HIDDEN + j);
#pragma unroll
            for (int k4 = 0; k4 < INPUT_SZ / 4; k4++) {
                float4 wi = __ldg(W0 + (size_t)(j           ) * (INPUT_SZ/4) + k4);
                float4 wg = __ldg(W0 + (size_t)(j + 2*HIDDEN) * (INPUT_SZ/4) + k4);
                float4 wo = __ldg(W0 + (size_t)(j + 3*HIDDEN) * (INPUT_SZ/4) + k4);
                const float x0 = xr[4*k4+0], x1 = xr[4*k4+1];
                const float x2 = xr[4*k4+2], x3 = xr[4*k4+3];
                ai = fmaf(wi.x, x0, ai); ai = fmaf(wi.y, x1, ai);
                ai = fmaf(wi.z, x2, ai); ai = fmaf(wi.w, x3, ai);
                ag = fmaf(wg.x, x0, ag); ag = fmaf(wg.y, x1, ag);
                ag = fmaf(wg.z, x2, ag); ag = fmaf(wg.w, x3, ag);
                ao = fmaf(wo.x, x0, ao); ao = fmaf(wo.y, x1, ao);
                ao = fmaf(wo.z, x2, ao); ao = fmaf(wo.w, x3, ao);
            }
            float c0 = fsig(ai) * ftanh(ag);
            hs[j * TPB + t] = fsig(ao) * ftanh(c0);
        }
    }

    // ---- layer 1 + heads fused: accumulate policy/value as each h1[j] is produced ----
    float pacc[NUM_ACT];
#pragma unroll
    for (int a = 0; a < NUM_ACT; a++) pacc[a] = __ldg(bp + a);
    float vacc = __ldg(bv);

    {
        const float4* W1 = reinterpret_cast<const float4*>(Wih1);
#pragma unroll 2
        for (int j = 0; j < HIDDEN; j++) {
            float ai = __ldg(bih1 + j)            + __ldg(bhh1 + j);
            float ag = __ldg(bih1 + 2*HIDDEN + j) + __ldg(bhh1 + 2*HIDDEN + j);
            float ao = __ldg(bih1 + 3*HIDDEN + j) + __ldg(bhh1 + 3*HIDDEN + j);
#pragma unroll
            for (int k4 = 0; k4 < HIDDEN / 4; k4++) {
                float4 wi = __ldg(W1 + (size_t)(j           ) * (HIDDEN/4) + k4);
                float4 wg = __ldg(W1 + (size_t)(j + 2*HIDDEN) * (HIDDEN/4) + k4);
                float4 wo = __ldg(W1 + (size_t)(j + 3*HIDDEN) * (HIDDEN/4) + k4);
                const float h0 = hs[(4*k4+0) * TPB + t];
                const float h1 = hs[(4*k4+1) * TPB + t];
                const float h2 = hs[(4*k4+2) * TPB + t];
                const float h3 = hs[(4*k4+3) * TPB + t];
                ai = fmaf(wi.x, h0, ai); ai = fmaf(wi.y, h1, ai);
                ai = fmaf(wi.z, h2, ai); ai = fmaf(wi.w, h3, ai);
                ag = fmaf(wg.x, h0, ag); ag = fmaf(wg.y, h1, ag);
                ag = fmaf(wg.z, h2, ag); ag = fmaf(wg.w, h3, ag);
                ao = fmaf(wo.x, h0, ao); ao = fmaf(wo.y, h1, ao);
                ao = fmaf(wo.z, h2, ao); ao = fmaf(wo.w, h3, ao);
            }
            float c1  = fsig(ai) * ftanh(ag);
            float h1v = fsig(ao) * ftanh(c1);
#pragma unroll
            for (int a = 0; a < NUM_ACT; a++)
                pacc[a] = fmaf(h1v, __ldg(Wp + a * HIDDEN + j), pacc[a]);
            vacc = fmaf(h1v, __ldg(Wv + j), vacc);
        }
    }

    // ---- write outputs: policy [B,16] then value [B,1] ----
    {
        float4* po = reinterpret_cast<float4*>(out_policy + (size_t)e * NUM_ACT);
#pragma unroll
        for (int a4 = 0; a4 < NUM_ACT / 4; a4++)
            po[a4] = make_float4(pacc[4*a4+0], pacc[4*a4+1], pacc[4*a4+2], pacc[4*a4+3]);
        out_value[e] = vacc;
    }
}

extern "C" void kernel_launch(void* const* d_in, const int* in_sizes, int n_in,
                              void* d_out, int out_size)
{
    (void)in_sizes; (void)n_in; (void)out_size;
    // metadata order (setup_inputs dict order):
    // 0:x 1:Wih0 2:Whh0(dead) 3:bih0 4:bhh0 5:Wih1 6:Whh1(dead) 7:bih1 8:bhh1
    // 9:Wp 10:bp 11:Wv 12:bv
    const float* x    = (const float*)d_in[0];
    const float* Wih0 = (const float*)d_in[1];
    const float* bih0 = (const float*)d_in[3];
    const float* bhh0 = (const float*)d_in[4];
    const float* Wih1 = (const float*)d_in[5];
    const float* bih1 = (const float*)d_in[7];
    const float* bhh1 = (const float*)d_in[8];
    const float* Wp   = (const float*)d_in[9];
    const float* bp   = (const float*)d_in[10];
    const float* Wv   = (const float*)d_in[11];
    const float* bv   = (const float*)d_in[12];

    float* out        = (float*)d_out;
    float* out_policy = out;                               // [B, 16]
    float* out_value  = out + (size_t)BATCH_N * NUM_ACT;   // [B, 1]

    const int smem_bytes = HIDDEN * TPB * (int)sizeof(float);  // 64 KB -> opt-in
    cudaFuncSetAttribute((const void*)lstm_policy_kernel,
                         cudaFuncAttributeMaxDynamicSharedMemorySize, smem_bytes);

    lstm_policy_kernel<<<BATCH_N / TPB, TPB, smem_bytes>>>(
        x, Wih0, bih0, bhh0, Wih1, bih1, bhh1, Wp, bp, Wv, bv,
        out_policy, out_value);
}

// round 3
// speedup vs baseline: 1.4753x; 1.4753x over previous
#include <cuda_runtime.h>
#include <math.h>

#define HIDDEN      128
#define INPUT_SZ    64
#define NUM_ACT     16
#define BATCH_N     65536
#define TPB         256
#define BM          64            // batch rows per block
#define PAIRS       32            // BM/2 f32x2 pairs
#define XS_STRIDE   66            // ull (=float2) per xs row: 64 + 2 pad
#define HS_STRIDE   130           // ull per hs row: 128 + 2 pad

typedef unsigned long long ull;

// ---------------- f32x2 packed helpers (sm_103a FFMA2 path) ----------------
__device__ __forceinline__ ull pk2(float x, float y) {
    ull r; asm("mov.b64 %0, {%1, %2};" : "=l"(r) : "f"(x), "f"(y)); return r;
}
__device__ __forceinline__ ull dup2(float x) { return pk2(x, x); }
__device__ __forceinline__ float2 up2(ull v) {
    float2 f; asm("mov.b64 {%0, %1}, %2;" : "=f"(f.x), "=f"(f.y) : "l"(v)); return f;
}
__device__ __forceinline__ void fma2(ull& d, ull a, ull b) {
    asm("fma.rn.f32x2 %0, %1, %2, %3;" : "=l"(d) : "l"(a), "l"(b), "l"(d));
}

// ---------------- activations (accurate path, ~2ulp) ----------------
__device__ __forceinline__ float fsig(float x) {
    return __fdividef(1.0f, 1.0f + __expf(-x));
}
__device__ __forceinline__ float ftanh(float x) {
    float ax = fabsf(x);
    float e  = __expf(-2.0f * ax);
    float t  = __fdividef(1.0f - e, 1.0f + e);
    return copysignf(t, x);
}
__device__ __forceinline__ float hcell(float i, float g, float o) {
    float c = fsig(i) * ftanh(g);
    return fsig(o) * ftanh(c);
}

// row offsets of the live gates inside the 4H weight/bias blocks (i, g, o)
__device__ __forceinline__ int grow_of(int g) {
    return (g == 0) ? 0 : (g == 1) ? 2 * HIDDEN : 3 * HIDDEN;
}

// init accumulators with (bih + bhh), replicated in both pack halves
__device__ __forceinline__ void init_acc(ull acc[4][3][4],
                                         const float* __restrict__ bih,
                                         const float* __restrict__ bhh, int jb) {
#pragma unroll
    for (int g = 0; g < 3; g++) {
        const int gr = grow_of(g);
#pragma unroll
        for (int jj = 0; jj < 4; jj++) {
            float b = __ldg(bih + gr + jb + jj) + __ldg(bhh + gr + jb + jj);
            ull bb = dup2(b);
#pragma unroll
            for (int pp = 0; pp < 4; pp++) acc[jj][g][pp] = bb;
        }
    }
}

// core GEMM phase: acc[jj][g][pp] += sum_k W[gr+jb+jj][k] * h[pair][k]
template <int NK4>
__device__ __forceinline__ void mm_layer(const float4* __restrict__ W, int kq,
                                         const ull* __restrict__ hsrc, int hstr,
                                         int mgp, int jb, ull acc[4][3][4]) {
#pragma unroll 1
    for (int k4 = 0; k4 < NK4; k4++) {
        ulonglong2 ha[4], hb[4];
#pragma unroll
        for (int pp = 0; pp < 4; pp++) {
            const ulonglong2* hp =
                reinterpret_cast<const ulonglong2*>(hsrc + (mgp + pp) * hstr + 4 * k4);
            ha[pp] = hp[0];
            hb[pp] = hp[1];
        }
#pragma unroll
        for (int g = 0; g < 3; g++) {
            const int gr = grow_of(g);
            float4 w[4];
#pragma unroll
            for (int jj = 0; jj < 4; jj++)
                w[jj] = __ldg(W + (size_t)(gr + jb + jj) * kq + k4);
#pragma unroll
            for (int jj = 0; jj < 4; jj++) {
#pragma unroll
                for (int kk = 0; kk < 4; kk++) {
                    float ws = (kk == 0) ? w[jj].x : (kk == 1) ? w[jj].y
                             : (kk == 2) ? w[jj].z : w[jj].w;
                    ull wp = dup2(ws);
#pragma unroll
                    for (int pp = 0; pp < 4; pp++) {
                        ull hv = (kk == 0) ? ha[pp].x : (kk == 1) ? ha[pp].y
                               : (kk == 2) ? hb[pp].x : hb[pp].y;
                        fma2(acc[jj][g][pp], wp, hv);
                    }
                }
            }
        }
    }
}

// activations + store h pairs to smem tile
__device__ __forceinline__ void act_store(ull acc[4][3][4], ull* __restrict__ hdst,
                                          int mgp, int jb) {
#pragma unroll
    for (int pp = 0; pp < 4; pp++) {
        ull row[4];
#pragma unroll
        for (int jj = 0; jj < 4; jj++) {
            float2 i2 = up2(acc[jj][0][pp]);
            float2 g2 = up2(acc[jj][1][pp]);
            float2 o2 = up2(acc[jj][2][pp]);
            row[jj] = pk2(hcell(i2.x, g2.x, o2.x), hcell(i2.y, g2.y, o2.y));
        }
        ull* dst = hdst + (mgp + pp) * HS_STRIDE + jb;
        reinterpret_cast<ulonglong2*>(dst)[0] = make_ulonglong2(row[0], row[1]);
        reinterpret_cast<ulonglong2*>(dst)[1] = make_ulonglong2(row[2], row[3]);
    }
}

extern "C" __global__ void __launch_bounds__(TPB, 1)
lstm_policy_kernel(const float* __restrict__ x,
                   const float* __restrict__ Wih0,
                   const float* __restrict__ bih0,
                   const float* __restrict__ bhh0,
                   const float* __restrict__ Wih1,
                   const float* __restrict__ bih1,
                   const float* __restrict__ bhh1,
                   const float* __restrict__ Wp,
                   const float* __restrict__ bp,
                   const float* __restrict__ Wv,
                   const float* __restrict__ bv,
                   float* __restrict__ out_policy,
                   float* __restrict__ out_value)
{
    extern __shared__ ull sm[];
    ull* xs = sm;                        // [PAIRS][XS_STRIDE]  (x pairs)
    ull* h0 = sm + PAIRS * XS_STRIDE;    // [PAIRS][HS_STRIDE]  (h0 pairs)
    ull* h1 = h0 + PAIRS * HS_STRIDE;    // [PAIRS][HS_STRIDE]  (h1 pairs)

    const int tid  = threadIdx.x;
    const int base = blockIdx.x * BM;    // global batch base of this block
    const int mg   = tid & 7;            // 8 m-groups of 4 pairs
    const int jg   = tid >> 3;           // 32 j-groups of 4 rows
    const int mgp  = mg * 4;
    const int jb   = jg * 4;

    // ---- stage x into pair-interleaved smem: xs[p][k] = (x[2p][k], x[2p+1][k]) ----
#pragma unroll
    for (int it = 0; it < 2; it++) {
        int idx = tid + it * TPB;        // 512 units = 32 pairs x 16 k4
        int p  = idx >> 4;
        int k4 = idx & 15;
        const float4* xr = reinterpret_cast<const float4*>(
                               x + (size_t)(base + 2 * p) * INPUT_SZ) + k4;
        float4 a = __ldg(xr);
        float4 b = __ldg(xr + INPUT_SZ / 4);     // next batch row
        ull* dst = xs + p * XS_STRIDE + 4 * k4;
        reinterpret_cast<ulonglong2*>(dst)[0] = make_ulonglong2(pk2(a.x, b.x), pk2(a.y, b.y));
        reinterpret_cast<ulonglong2*>(dst)[1] = make_ulonglong2(pk2(a.z, b.z), pk2(a.w, b.w));
    }
    __syncthreads();

    // ---- layer 0 ----
    {
        ull acc[4][3][4];
        init_acc(acc, bih0, bhh0, jb);
        mm_layer<INPUT_SZ / 4>(reinterpret_cast<const float4*>(Wih0), INPUT_SZ / 4,
                               xs, XS_STRIDE, mgp, jb, acc);
        act_store(acc, h0, mgp, jb);
    }
    __syncthreads();

    // ---- layer 1 ----
    {
        ull acc[4][3][4];
        init_acc(acc, bih1, bhh1, jb);
        mm_layer<HIDDEN / 4>(reinterpret_cast<const float4*>(Wih1), HIDDEN / 4,
                             h0, HS_STRIDE, mgp, jb, acc);
        act_store(acc, h1, mgp, jb);
    }
    __syncthreads();

    // ---- heads: each warp handles 2 policy rows (warp 0 also the value head) ----
    {
        const int lane = tid & 31;          // pair index
        const int wg   = tid >> 5;          // 0..7
        const int a0   = wg * 2;
        const int a1   = a0 + 1;

        ull acc0 = dup2(__ldg(bp + a0));
        ull acc1 = dup2(__ldg(bp + a1));
        ull accv = dup2(__ldg(bv));

        const ull* hrow = h1 + lane * HS_STRIDE;
        const float4* Wp4 = reinterpret_cast<const float4*>(Wp);
        const float4* Wv4 = reinterpret_cast<const float4*>(Wv);

#pragma unroll 2
        for (int k4 = 0; k4 < HIDDEN / 4; k4++) {
            const ulonglong2* hp = reinterpret_cast<const ulonglong2*>(hrow + 4 * k4);
            ulonglong2 hA = hp[0];
            ulonglong2 hB = hp[1];
            float4 w0 = __ldg(Wp4 + a0 * (HIDDEN / 4) + k4);
            float4 w1 = __ldg(Wp4 + a1 * (HIDDEN / 4) + k4);
            fma2(acc0, dup2(w0.x), hA.x); fma2(acc0, dup2(w0.y), hA.y);
            fma2(acc0, dup2(w0.z), hB.x); fma2(acc0, dup2(w0.w), hB.y);
            fma2(acc1, dup2(w1.x), hA.x); fma2(acc1, dup2(w1.y), hA.y);
            fma2(acc1, dup2(w1.z), hB.x); fma2(acc1, dup2(w1.w), hB.y);
            if (wg == 0) {
                float4 wv = __ldg(Wv4 + k4);
                fma2(accv, dup2(wv.x), hA.x); fma2(accv, dup2(wv.y), hA.y);
                fma2(accv, dup2(wv.z), hB.x); fma2(accv, dup2(wv.w), hB.y);
            }
        }

        const size_t b0 = (size_t)base + 2 * lane;
        float2 r0 = up2(acc0), r1 = up2(acc1);
        out_policy[b0 * NUM_ACT + a0]       = r0.x;
        out_policy[(b0 + 1) * NUM_ACT + a0] = r0.y;
        out_policy[b0 * NUM_ACT + a1]       = r1.x;
        out_policy[(b0 + 1) * NUM_ACT + a1] = r1.y;
        if (wg == 0) {
            float2 rv = up2(accv);
            out_value[b0]     = rv.x;
            out_value[b0 + 1] = rv.y;
        }
    }
}

extern "C" void kernel_launch(void* const* d_in, const int* in_sizes, int n_in,
                              void* d_out, int out_size)
{
    (void)in_sizes; (void)n_in; (void)out_size;
    // 0:x 1:Wih0 2:Whh0(dead) 3:bih0 4:bhh0 5:Wih1 6:Whh1(dead) 7:bih1 8:bhh1
    // 9:Wp 10:bp 11:Wv 12:bv
    const float* x    = (const float*)d_in[0];
    const float* Wih0 = (const float*)d_in[1];
    const float* bih0 = (const float*)d_in[3];
    const float* bhh0 = (const float*)d_in[4];
    const float* Wih1 = (const float*)d_in[5];
    const float* bih1 = (const float*)d_in[7];
    const float* bhh1 = (const float*)d_in[8];
    const float* Wp   = (const float*)d_in[9];
    const float* bp   = (const float*)d_in[10];
    const float* Wv   = (const float*)d_in[11];
    const float* bv   = (const float*)d_in[12];

    float* out        = (float*)d_out;
    float* out_policy = out;                               // [B, 16]
    float* out_value  = out + (size_t)BATCH_N * NUM_ACT;   // [B, 1]

    const int smem_bytes =
        (PAIRS * XS_STRIDE + 2 * PAIRS * HS_STRIDE) * (int)sizeof(ull);   // 83456 B
    cudaFuncSetAttribute((const void*)lstm_policy_kernel,
                         cudaFuncAttributeMaxDynamicSharedMemorySize, smem_bytes);

    lstm_policy_kernel<<<BATCH_N / BM, TPB, smem_bytes>>>(
        x, Wih0, bih0, bhh0, Wih1, bih1, bhh1, Wp, bp, Wv, bv,
        out_policy, out_value);
}

// round 5
// speedup vs baseline: 8.7145x; 5.9068x over previous
#include <cuda_runtime.h>
#include <cuda_fp16.h>
#include <cstdint>
#include <math.h>

#define HIDDEN    128
#define INPUT_SZ  64
#define NUM_ACT   16
#define BATCH_N   65536
#define TPB       256
#define BM        128

// padded strides (in halfs) -> conflict-free ldmatrix (stride%32 words == 4)
#define XSTR   72     // x: 64 + 8
#define W0STR  72
#define W1STR  136    // 128 + 8
#define WHSTR  136
#define HSTR   136
#define BUFSTR 20     // head reduce buffer stride (floats)

// smem layout (bytes)
#define SM_X    0                      // 128*72*2   = 18432   (aliased by BUF later)
#define SM_BUF  0                      // 128*20*4   = 10240
#define SM_W0   18432                  // 3*128*72*2 = 55296
#define SM_W1   73728                  // 3*128*136*2= 104448
#define SM_WH   178176                 // 32*136*2   = 8704
#define SM_H0   186880                 // 128*136*2  = 34816
#define SM_B0   221696                 // 384 f32
#define SM_B1   223232                 // 384 f32
#define SM_BP   224768                 // 16 f32
#define SM_BV   224832                 // 1 f32 (+pad)
#define SM_TOTAL 224896

__device__ __forceinline__ uint32_t smem_u32(const void* p) {
    uint32_t a;
    asm("{ .reg .u64 t; cvta.to.shared.u64 t, %1; cvt.u32.u64 %0, t; }"
        : "=r"(a) : "l"(p));
    return a;
}
__device__ __forceinline__ void ldsm4(uint32_t& r0, uint32_t& r1, uint32_t& r2,
                                      uint32_t& r3, uint32_t addr) {
    asm volatile("ldmatrix.sync.aligned.m8n8.x4.shared.b16 {%0,%1,%2,%3}, [%4];"
                 : "=r"(r0), "=r"(r1), "=r"(r2), "=r"(r3) : "r"(addr));
}
__device__ __forceinline__ void ldsm2(uint32_t& r0, uint32_t& r1, uint32_t addr) {
    asm volatile("ldmatrix.sync.aligned.m8n8.x2.shared.b16 {%0,%1}, [%2];"
                 : "=r"(r0), "=r"(r1) : "r"(addr));
}
__device__ __forceinline__ void mma16816(float* d, const uint32_t* a,
                                         uint32_t b0, uint32_t b1) {
    asm volatile(
        "mma.sync.aligned.m16n8k16.row.col.f32.f16.f16.f32 "
        "{%0,%1,%2,%3}, {%4,%5,%6,%7}, {%8,%9}, {%0,%1,%2,%3};"
        : "+f"(d[0]), "+f"(d[1]), "+f"(d[2]), "+f"(d[3])
        : "r"(a[0]), "r"(a[1]), "r"(a[2]), "r"(a[3]), "r"(b0), "r"(b1));
}

__device__ __forceinline__ float fsig(float x) {
    return __fdividef(1.0f, 1.0f + __expf(-x));
}
__device__ __forceinline__ float ftanh(float x) {
    float ax = fabsf(x);
    float e  = __expf(-2.0f * ax);
    float t  = __fdividef(1.0f - e, 1.0f + e);
    return copysignf(t, x);
}
__device__ __forceinline__ float hcell(float i, float g, float o) {
    float c = fsig(i) * ftanh(g);
    return fsig(o) * ftanh(c);
}
__device__ __forceinline__ int grow_of(int g) {   // live gates i,g,o in 4H blocks
    return (g == 0) ? 0 : (g == 1) ? 2 * HIDDEN : 3 * HIDDEN;
}
__device__ __forceinline__ uint32_t h2u(float a, float b) {
    __half2 h = __floats2half2_rn(a, b);
    return *reinterpret_cast<uint32_t*>(&h);
}

extern "C" __global__ void __launch_bounds__(TPB, 1)
lstm_policy_mma(const float* __restrict__ x,
                const float* __restrict__ Wih0,
                const float* __restrict__ bih0,
                const float* __restrict__ bhh0,
                const float* __restrict__ Wih1,
                const float* __restrict__ bih1,
                const float* __restrict__ bhh1,
                const float* __restrict__ Wp,
                const float* __restrict__ bp,
                const float* __restrict__ Wv,
                const float* __restrict__ bv,
                float* __restrict__ out_policy,
                float* __restrict__ out_value)
{
    extern __shared__ char smem[];
    const uint32_t sb = smem_u32(smem);
    const int tid  = threadIdx.x;
    const int lane = tid & 31;
    const int wid  = tid >> 5;
    const int mg   = wid >> 1;         // 0..3 : 32-row m-group
    const int jh   = wid & 1;          // 0..1 : 64-col j-half
    const int base = blockIdx.x * BM;

    float* b0_s = reinterpret_cast<float*>(smem + SM_B0);
    float* b1_s = reinterpret_cast<float*>(smem + SM_B1);
    float* bp_s = reinterpret_cast<float*>(smem + SM_BP);
    float* bv_s = reinterpret_cast<float*>(smem + SM_BV);

    // lane decomposition for ldmatrix address patterns
    const int rA   = lane & 15;                    // A: row in 16-row tile
    const int kA   = ((lane >> 4) & 1) * 8;        // A: k offset
    const int rB   = (lane & 7) + ((lane >> 4) & 1) * 8;  // B: row (n) in 16
    const int kB   = ((lane >> 3) & 1) * 8;        // B: k offset
    const int qr   = lane >> 2;                    // acc row-in-tile
    const int qc   = (lane & 3) * 2;               // acc col-in-tile

    // ================= staging (fp32 -> fp16 smem) =================
    // x: 128 rows x 64 -> [row*XSTR]
#pragma unroll
    for (int it = 0; it < 2; it++) {
        int idx = tid + it * TPB;            // 512 slots
        int row = idx >> 2, c = idx & 3;
        const float4* src = reinterpret_cast<const float4*>(
            x + (size_t)(base + row) * INPUT_SZ) + c * 4;
        float4 v0 = __ldg(src), v1 = __ldg(src + 1), v2 = __ldg(src + 2), v3 = __ldg(src + 3);
        uint32_t* dst = reinterpret_cast<uint32_t*>(smem + SM_X + (row * XSTR + c * 16) * 2);
        dst[0] = h2u(v0.x, v0.y); dst[1] = h2u(v0.z, v0.w);
        dst[2] = h2u(v1.x, v1.y); dst[3] = h2u(v1.z, v1.w);
        dst[4] = h2u(v2.x, v2.y); dst[5] = h2u(v2.z, v2.w);
        dst[6] = h2u(v3.x, v3.y); dst[7] = h2u(v3.z, v3.w);
    }
    // W0: 384 rows x 64
#pragma unroll
    for (int it = 0; it < 6; it++) {
        int idx = tid + it * TPB;            // 1536 slots
        int rr = idx >> 2, c = idx & 3;
        int g = rr >> 7, j = rr & 127;
        const float4* src = reinterpret_cast<const float4*>(
            Wih0 + (size_t)(grow_of(g) + j) * INPUT_SZ) + c * 4;
        float4 v0 = __ldg(src), v1 = __ldg(src + 1), v2 = __ldg(src + 2), v3 = __ldg(src + 3);
        uint32_t* dst = reinterpret_cast<uint32_t*>(smem + SM_W0 + (rr * W0STR + c * 16) * 2);
        dst[0] = h2u(v0.x, v0.y); dst[1] = h2u(v0.z, v0.w);
        dst[2] = h2u(v1.x, v1.y); dst[3] = h2u(v1.z, v1.w);
        dst[4] = h2u(v2.x, v2.y); dst[5] = h2u(v2.z, v2.w);
        dst[6] = h2u(v3.x, v3.y); dst[7] = h2u(v3.z, v3.w);
    }
    // W1: 384 rows x 128
#pragma unroll
    for (int it = 0; it < 12; it++) {
        int idx = tid + it * TPB;            // 3072 slots
        int rr = idx >> 3, c = idx & 7;
        int g = rr >> 7, j = rr & 127;
        const float4* src = reinterpret_cast<const float4*>(
            Wih1 + (size_t)(grow_of(g) + j) * HIDDEN) + c * 4;
        float4 v0 = __ldg(src), v1 = __ldg(src + 1), v2 = __ldg(src + 2), v3 = __ldg(src + 3);
        uint32_t* dst = reinterpret_cast<uint32_t*>(smem + SM_W1 + (rr * W1STR + c * 16) * 2);
        dst[0] = h2u(v0.x, v0.y); dst[1] = h2u(v0.z, v0.w);
        dst[2] = h2u(v1.x, v1.y); dst[3] = h2u(v1.z, v1.w);
        dst[4] = h2u(v2.x, v2.y); dst[5] = h2u(v2.z, v2.w);
        dst[6] = h2u(v3.x, v3.y); dst[7] = h2u(v3.z, v3.w);
    }
    // WH: 32 rows x 128 (0-15 Wp, 16 Wv, 17-31 zero)
    {
        int row = tid >> 3, c = tid & 7;     // 256 slots
        float4 v0, v1, v2, v3;
        if (row < NUM_ACT) {
            const float4* src = reinterpret_cast<const float4*>(
                Wp + (size_t)row * HIDDEN) + c * 4;
            v0 = __ldg(src); v1 = __ldg(src + 1); v2 = __ldg(src + 2); v3 = __ldg(src + 3);
        } else if (row == NUM_ACT) {
            const float4* src = reinterpret_cast<const float4*>(Wv) + c * 4;
            v0 = __ldg(src); v1 = __ldg(src + 1); v2 = __ldg(src + 2); v3 = __ldg(src + 3);
        } else {
            v0 = v1 = v2 = v3 = make_float4(0.f, 0.f, 0.f, 0.f);
        }
        uint32_t* dst = reinterpret_cast<uint32_t*>(smem + SM_WH + (row * WHSTR + c * 16) * 2);
        dst[0] = h2u(v0.x, v0.y); dst[1] = h2u(v0.z, v0.w);
        dst[2] = h2u(v1.x, v1.y); dst[3] = h2u(v1.z, v1.w);
        dst[4] = h2u(v2.x, v2.y); dst[5] = h2u(v2.z, v2.w);
        dst[6] = h2u(v3.x, v3.y); dst[7] = h2u(v3.z, v3.w);
    }
    // biases (gate-major [g*128+j])
#pragma unroll
    for (int it = 0; it < 2; it++) {
        int idx = tid + it * TPB;
        if (idx < 384) {
            int g = idx >> 7, j = idx & 127;
            int row = grow_of(g) + j;
            b0_s[idx] = __ldg(bih0 + row) + __ldg(bhh0 + row);
            b1_s[idx] = __ldg(bih1 + row) + __ldg(bhh1 + row);
        }
    }
    if (tid < NUM_ACT) bp_s[tid] = __ldg(bp + tid);
    if (tid == 0) bv_s[0] = __ldg(bv);
    __syncthreads();

    // ================= layer 0: gates = x @ W0^T, -> h0 smem =================
#pragma unroll 1
    for (int jq = 0; jq < 2; jq++) {
        float acc[2][3][4][4];
#pragma unroll
        for (int mt = 0; mt < 2; mt++)
#pragma unroll
            for (int g = 0; g < 3; g++)
#pragma unroll
                for (int jt = 0; jt < 4; jt++)
#pragma unroll
                    for (int e = 0; e < 4; e++) acc[mt][g][jt][e] = 0.f;

#pragma unroll 1
        for (int ks = 0; ks < 4; ks++) {
            uint32_t a[2][4];
#pragma unroll
            for (int mt = 0; mt < 2; mt++) {
                uint32_t addr = sb + SM_X +
                    (uint32_t)(((mg * 32 + mt * 16 + rA) * XSTR + ks * 16 + kA) * 2);
                ldsm4(a[mt][0], a[mt][1], a[mt][2], a[mt][3], addr);
            }
#pragma unroll
            for (int g = 0; g < 3; g++) {
#pragma unroll
                for (int jp = 0; jp < 2; jp++) {
                    int jb = jh * 64 + jq * 32 + jp * 16;
                    uint32_t addr = sb + SM_W0 +
                        (uint32_t)(((g * 128 + jb + rB) * W0STR + ks * 16 + kB) * 2);
                    uint32_t b0, b1, b2, b3;
                    ldsm4(b0, b1, b2, b3, addr);
#pragma unroll
                    for (int mt = 0; mt < 2; mt++) {
                        mma16816(acc[mt][g][2 * jp],     a[mt], b0, b1);
                        mma16816(acc[mt][g][2 * jp + 1], a[mt], b2, b3);
                    }
                }
            }
        }
        // epilogue -> h0 fp16 smem
#pragma unroll
        for (int mt = 0; mt < 2; mt++) {
#pragma unroll
            for (int jt = 0; jt < 4; jt++) {
                int j0 = jh * 64 + jq * 32 + jt * 8 + qc;
                float2 bi = *reinterpret_cast<const float2*>(b0_s + j0);
                float2 bg = *reinterpret_cast<const float2*>(b0_s + 128 + j0);
                float2 bo = *reinterpret_cast<const float2*>(b0_s + 256 + j0);
                float v0 = hcell(acc[mt][0][jt][0] + bi.x, acc[mt][1][jt][0] + bg.x,
                                 acc[mt][2][jt][0] + bo.x);
                float v1 = hcell(acc[mt][0][jt][1] + bi.y, acc[mt][1][jt][1] + bg.y,
                                 acc[mt][2][jt][1] + bo.y);
                float v2 = hcell(acc[mt][0][jt][2] + bi.x, acc[mt][1][jt][2] + bg.x,
                                 acc[mt][2][jt][2] + bo.x);
                float v3 = hcell(acc[mt][0][jt][3] + bi.y, acc[mt][1][jt][3] + bg.y,
                                 acc[mt][2][jt][3] + bo.y);
                int ra = mg * 32 + mt * 16 + qr;
                *reinterpret_cast<uint32_t*>(smem + SM_H0 + (ra * HSTR + j0) * 2)
                    = h2u(v0, v1);
                *reinterpret_cast<uint32_t*>(smem + SM_H0 + ((ra + 8) * HSTR + j0) * 2)
                    = h2u(v2, v3);
            }
        }
    }
    __syncthreads();

    // ================= layer 1 + h1 as in-register A-frags =================
    uint32_t hfrag[2][4][4];
#pragma unroll
    for (int jq = 0; jq < 2; jq++) {
        float acc[2][3][4][4];
#pragma unroll
        for (int mt = 0; mt < 2; mt++)
#pragma unroll
            for (int g = 0; g < 3; g++)
#pragma unroll
                for (int jt = 0; jt < 4; jt++)
#pragma unroll
                    for (int e = 0; e < 4; e++) acc[mt][g][jt][e] = 0.f;

#pragma unroll 1
        for (int ks = 0; ks < 8; ks++) {
            uint32_t a[2][4];
#pragma unroll
            for (int mt = 0; mt < 2; mt++) {
                uint32_t addr = sb + SM_H0 +
                    (uint32_t)(((mg * 32 + mt * 16 + rA) * HSTR + ks * 16 + kA) * 2);
                ldsm4(a[mt][0], a[mt][1], a[mt][2], a[mt][3], addr);
            }
#pragma unroll
            for (int g = 0; g < 3; g++) {
#pragma unroll
                for (int jp = 0; jp < 2; jp++) {
                    int jb = jh * 64 + jq * 32 + jp * 16;
                    uint32_t addr = sb + SM_W1 +
                        (uint32_t)(((g * 128 + jb + rB) * W1STR + ks * 16 + kB) * 2);
                    uint32_t b0, b1, b2, b3;
                    ldsm4(b0, b1, b2, b3, addr);
#pragma unroll
                    for (int mt = 0; mt < 2; mt++) {
                        mma16816(acc[mt][g][2 * jp],     a[mt], b0, b1);
                        mma16816(acc[mt][g][2 * jp + 1], a[mt], b2, b3);
                    }
                }
            }
        }
        // epilogue: hcell -> packed A-fragments (k-tile = jq*2 + jp)
#pragma unroll
        for (int mt = 0; mt < 2; mt++) {
#pragma unroll
            for (int jp = 0; jp < 2; jp++) {
                int kt = jq * 2 + jp;
                float v[2][4];
#pragma unroll
                for (int half = 0; half < 2; half++) {
                    int jt = 2 * jp + half;
                    int j0 = jh * 64 + jq * 32 + jt * 8 + qc;
                    float2 bi = *reinterpret_cast<const float2*>(b1_s + j0);
                    float2 bg = *reinterpret_cast<const float2*>(b1_s + 128 + j0);
                    float2 bo = *reinterpret_cast<const float2*>(b1_s + 256 + j0);
                    v[half][0] = hcell(acc[mt][0][jt][0] + bi.x, acc[mt][1][jt][0] + bg.x,
                                       acc[mt][2][jt][0] + bo.x);
                    v[half][1] = hcell(acc[mt][0][jt][1] + bi.y, acc[mt][1][jt][1] + bg.y,
                                       acc[mt][2][jt][1] + bo.y);
                    v[half][2] = hcell(acc[mt][0][jt][2] + bi.x, acc[mt][1][jt][2] + bg.x,
                                       acc[mt][2][jt][2] + bo.x);
                    v[half][3] = hcell(acc[mt][0][jt][3] + bi.y, acc[mt][1][jt][3] + bg.y,
                                       acc[mt][2][jt][3] + bo.y);
                }
                hfrag[mt][kt][0] = h2u(v[0][0], v[0][1]);
                hfrag[mt][kt][1] = h2u(v[0][2], v[0][3]);
                hfrag[mt][kt][2] = h2u(v[1][0], v[1][1]);
                hfrag[mt][kt][3] = h2u(v[1][2], v[1][3]);
            }
        }
    }

    // ================= heads: [m x 17] = h1 @ WH^T (N padded to 24) ==========
    float hacc[2][3][4];
#pragma unroll
    for (int mt = 0; mt < 2; mt++)
#pragma unroll
        for (int nt = 0; nt < 3; nt++)
#pragma unroll
            for (int e = 0; e < 4; e++) hacc[mt][nt][e] = 0.f;

#pragma unroll
    for (int kt = 0; kt < 4; kt++) {
        int kg = jh * 64 + kt * 16;
        uint32_t b0, b1, b2, b3, c0, c1;
        uint32_t addr01 = sb + SM_WH + (uint32_t)(((rB) * WHSTR + kg + kB) * 2);
        ldsm4(b0, b1, b2, b3, addr01);
        uint32_t addr2 = sb + SM_WH +
            (uint32_t)(((16 + (lane & 7) + ((lane >> 3) & 1) * 0) * WHSTR + kg +
                        ((lane >> 3) & 1) * 8) * 2);
        ldsm2(c0, c1, addr2);
#pragma unroll
        for (int mt = 0; mt < 2; mt++) {
            mma16816(hacc[mt][0], hfrag[mt][kt], b0, b1);
            mma16816(hacc[mt][1], hfrag[mt][kt], b2, b3);
            mma16816(hacc[mt][2], hfrag[mt][kt], c0, c1);
        }
    }

    // ================= cross-warp (j-half) reduction + writeout =============
    float* buf = reinterpret_cast<float*>(smem + SM_BUF);
    if (jh == 0) {
#pragma unroll
        for (int mt = 0; mt < 2; mt++)
#pragma unroll
            for (int nt = 0; nt < 3; nt++)
#pragma unroll
                for (int e = 0; e < 4; e++) {
                    int n = nt * 8 + qc + (e & 1);
                    if (n < 17) {
                        int m = mg * 32 + mt * 16 + qr + ((e >= 2) ? 8 : 0);
                        buf[m * BUFSTR + n] = hacc[mt][nt][e];
                    }
                }
    }
    __syncthreads();
    if (jh == 1) {
#pragma unroll
        for (int mt = 0; mt < 2; mt++)
#pragma unroll
            for (int nt = 0; nt < 3; nt++)
#pragma unroll
                for (int e = 0; e < 4; e++) {
                    int n = nt * 8 + qc + (e & 1);
                    if (n < 17) {
                        int m = mg * 32 + mt * 16 + qr + ((e >= 2) ? 8 : 0);
                        buf[m * BUFSTR + n] += hacc[mt][nt][e];
                    }
                }
    }
    __syncthreads();

    {
        int row = tid >> 1, hn = tid & 1;          // 128 rows x 2 halves of 8
        const float* src = buf + row * BUFSTR + hn * 8;
        float4 o0 = make_float4(src[0] + bp_s[hn * 8 + 0], src[1] + bp_s[hn * 8 + 1],
                                src[2] + bp_s[hn * 8 + 2], src[3] + bp_s[hn * 8 + 3]);
        float4 o1 = make_float4(src[4] + bp_s[hn * 8 + 4], src[5] + bp_s[hn * 8 + 5],
                                src[6] + bp_s[hn * 8 + 6], src[7] + bp_s[hn * 8 + 7]);
        float4* dst = reinterpret_cast<float4*>(
            out_policy + (size_t)(base + row) * NUM_ACT + hn * 8);
        dst[0] = o0; dst[1] = o1;
        if (tid < BM)
            out_value[base + tid] = buf[tid * BUFSTR + 16] + bv_s[0];
    }
}

extern "C" void kernel_launch(void* const* d_in, const int* in_sizes, int n_in,
                              void* d_out, int out_size)
{
    (void)in_sizes; (void)n_in; (void)out_size;
    // 0:x 1:Wih0 2:Whh0(dead) 3:bih0 4:bhh0 5:Wih1 6:Whh1(dead) 7:bih1 8:bhh1
    // 9:Wp 10:bp 11:Wv 12:bv
    const float* x    = (const float*)d_in[0];
    const float* Wih0 = (const float*)d_in[1];
    const float* bih0 = (const float*)d_in[3];
    const float* bhh0 = (const float*)d_in[4];
    const float* Wih1 = (const float*)d_in[5];
    const float* bih1 = (const float*)d_in[7];
    const float* bhh1 = (const float*)d_in[8];
    const float* Wp   = (const float*)d_in[9];
    const float* bp   = (const float*)d_in[10];
    const float* Wv   = (const float*)d_in[11];
    const float* bv   = (const float*)d_in[12];

    float* out        = (float*)d_out;
    float* out_policy = out;
    float* out_value  = out + (size_t)BATCH_N * NUM_ACT;

    cudaFuncSetAttribute((const void*)lstm_policy_mma,
                         cudaFuncAttributeMaxDynamicSharedMemorySize, SM_TOTAL);

    lstm_policy_mma<<<BATCH_N / BM, TPB, SM_TOTAL>>>(
        x, Wih0, bih0, bhh0, Wih1, bih1, bhh1, Wp, bp, Wv, bv,
        out_policy, out_value);
}

// round 6
// speedup vs baseline: 10.3935x; 1.1927x over previous
#include <cuda_runtime.h>
#include <cuda_fp16.h>
#include <cstdint>
#include <math.h>

#define HIDDEN    128
#define INPUT_SZ  64
#define NUM_ACT   16
#define BATCH_N   65536
#define TPB       256
#define BM        128

// padded strides (in halfs) -> conflict-free ldmatrix
#define XSTR   72
#define W0STR  72
#define W1STR  136
#define WHSTR  136
#define HSTR   136
#define BUFSTR 20

// smem layout (bytes)
#define SM_X    0                      // 128*72*2   = 18432 (aliased by BUF later)
#define SM_BUF  0
#define SM_W0   18432                  // 3*128*72*2 = 55296
#define SM_W1   73728                  // 3*128*136*2= 104448
#define SM_WH   178176                 // 32*136*2   = 8704
#define SM_H0   186880                 // 128*136*2  = 34816
#define SM_B0   221696
#define SM_B1   223232
#define SM_BP   224768
#define SM_BV   224832
#define SM_TOTAL 224896

// ---------------- precomputed fp16 weights / f32 bias sums (device globals) --
__device__ __half gW0h[3 * 128 * 64];     // [g*128+j][64]
__device__ __half gW1h[3 * 128 * 128];    // [g*128+j][128]
__device__ __half gWHh[32 * 128];         // rows 0-15 Wp, 16 Wv, 17-31 zero
__device__ float  gB0[384], gB1[384], gBP[16], gBV[1];

__device__ __forceinline__ uint32_t smem_u32(const void* p) {
    uint32_t a;
    asm("{ .reg .u64 t; cvta.to.shared.u64 t, %1; cvt.u32.u64 %0, t; }"
        : "=r"(a) : "l"(p));
    return a;
}
__device__ __forceinline__ void cp16(uint32_t dst, const void* src) {
    asm volatile("cp.async.cg.shared.global [%0], [%1], 16;"
                 :: "r"(dst), "l"(src));
}
__device__ __forceinline__ void cp_commit() {
    asm volatile("cp.async.commit_group;" ::: "memory");
}
template <int N>
__device__ __forceinline__ void cp_wait() {
    asm volatile("cp.async.wait_group %0;" :: "n"(N) : "memory");
}
__device__ __forceinline__ void ldsm4(uint32_t& r0, uint32_t& r1, uint32_t& r2,
                                      uint32_t& r3, uint32_t addr) {
    asm volatile("ldmatrix.sync.aligned.m8n8.x4.shared.b16 {%0,%1,%2,%3}, [%4];"
                 : "=r"(r0), "=r"(r1), "=r"(r2), "=r"(r3) : "r"(addr));
}
__device__ __forceinline__ void ldsm2(uint32_t& r0, uint32_t& r1, uint32_t addr) {
    asm volatile("ldmatrix.sync.aligned.m8n8.x2.shared.b16 {%0,%1}, [%2];"
                 : "=r"(r0), "=r"(r1) : "r"(addr));
}
__device__ __forceinline__ void mma16816(float* d, const uint32_t* a,
                                         uint32_t b0, uint32_t b1) {
    asm volatile(
        "mma.sync.aligned.m16n8k16.row.col.f32.f16.f16.f32 "
        "{%0,%1,%2,%3}, {%4,%5,%6,%7}, {%8,%9}, {%0,%1,%2,%3};"
        : "+f"(d[0]), "+f"(d[1]), "+f"(d[2]), "+f"(d[3])
        : "r"(a[0]), "r"(a[1]), "r"(a[2]), "r"(a[3]), "r"(b0), "r"(b1));
}

// 6-MUFU hcell: sig(i)*tanh(g) = (2-B)/(A*B); h = (1-F)*rcp((1+F)*D)
__device__ __forceinline__ float hcell(float i, float g, float o) {
    i = fmaxf(i, -30.0f); g = fmaxf(g, -15.0f); o = fmaxf(o, -30.0f);
    float A = 1.0f + __expf(-i);
    float B = 1.0f + __expf(-2.0f * g);
    float c = (2.0f - B) * __fdividef(1.0f, A * B);   // sig(i)*tanh(g), in (-1,1)
    float F = __expf(-2.0f * c);
    float D = 1.0f + __expf(-o);
    return (1.0f - F) * __fdividef(1.0f, (1.0f + F) * D);
}
__device__ __forceinline__ int grow_of(int g) {   // live gates i,g,o in 4H blocks
    return (g == 0) ? 0 : (g == 1) ? 2 * HIDDEN : 3 * HIDDEN;
}
__device__ __forceinline__ uint32_t h2u(float a, float b) {
    __half2 h = __floats2half2_rn(a, b);
    return *reinterpret_cast<uint32_t*>(&h);
}

// =================== prep kernel: fp32 -> fp16 weights, bias sums ============
extern "C" __global__ void prep_weights(const float* __restrict__ Wih0,
                                        const float* __restrict__ Wih1,
                                        const float* __restrict__ Wp,
                                        const float* __restrict__ Wv,
                                        const float* __restrict__ bih0,
                                        const float* __restrict__ bhh0,
                                        const float* __restrict__ bih1,
                                        const float* __restrict__ bhh1,
                                        const float* __restrict__ bp,
                                        const float* __restrict__ bv)
{
    const int tid = blockIdx.x * blockDim.x + threadIdx.x;
    const int nt  = gridDim.x * blockDim.x;
    for (int idx = tid; idx < 3 * 128 * 64; idx += nt) {
        int rr = idx >> 6, c = idx & 63;
        int g = rr >> 7, j = rr & 127;
        gW0h[idx] = __float2half_rn(__ldg(Wih0 + (size_t)(grow_of(g) + j) * 64 + c));
    }
    for (int idx = tid; idx < 3 * 128 * 128; idx += nt) {
        int rr = idx >> 7, c = idx & 127;
        int g = rr >> 7, j = rr & 127;
        gW1h[idx] = __float2half_rn(__ldg(Wih1 + (size_t)(grow_of(g) + j) * 128 + c));
    }
    for (int idx = tid; idx < 32 * 128; idx += nt) {
        int row = idx >> 7, c = idx & 127;
        float v = (row < NUM_ACT) ? __ldg(Wp + row * 128 + c)
                : (row == NUM_ACT) ? __ldg(Wv + c) : 0.0f;
        gWHh[idx] = __float2half_rn(v);
    }
    for (int idx = tid; idx < 384; idx += nt) {
        int g = idx >> 7, j = idx & 127;
        int row = grow_of(g) + j;
        gB0[idx] = __ldg(bih0 + row) + __ldg(bhh0 + row);
        gB1[idx] = __ldg(bih1 + row) + __ldg(bhh1 + row);
    }
    if (tid < NUM_ACT) gBP[tid] = __ldg(bp + tid);
    if (tid == 0) gBV[0] = __ldg(bv);
}

// =================== main kernel =============================================
extern "C" __global__ void __launch_bounds__(TPB, 1)
lstm_policy_mma(const float* __restrict__ x,
                float* __restrict__ out_policy,
                float* __restrict__ out_value)
{
    extern __shared__ char smem[];
    const uint32_t sb = smem_u32(smem);
    const int tid  = threadIdx.x;
    const int lane = tid & 31;
    const int wid  = tid >> 5;
    const int mg   = wid >> 1;         // 0..3 : 32-row m-group
    const int jh   = wid & 1;          // 0..1 : 64-col j-half
    const int base = blockIdx.x * BM;

    float* b0_s = reinterpret_cast<float*>(smem + SM_B0);
    float* b1_s = reinterpret_cast<float*>(smem + SM_B1);
    float* bp_s = reinterpret_cast<float*>(smem + SM_BP);
    float* bv_s = reinterpret_cast<float*>(smem + SM_BV);

    const int rA   = lane & 15;
    const int kA   = ((lane >> 4) & 1) * 8;
    const int rB   = (lane & 7) + ((lane >> 4) & 1) * 8;
    const int kB   = ((lane >> 3) & 1) * 8;
    const int qr   = lane >> 2;
    const int qc   = (lane & 3) * 2;

    // ===== async staging: group A = W0, group B = W1 + WH (fp16 copies) =====
#pragma unroll
    for (int it = 0; it < 12; it++) {              // W0: 3072 16B chunks
        int id = tid + it * TPB;
        int rr = id >> 3, c = id & 7;
        cp16(sb + SM_W0 + (uint32_t)((rr * W0STR + c * 8) * 2),
             gW0h + rr * 64 + c * 8);
    }
    cp_commit();
#pragma unroll
    for (int it = 0; it < 24; it++) {              // W1: 6144 chunks
        int id = tid + it * TPB;
        int rr = id >> 4, c = id & 15;
        cp16(sb + SM_W1 + (uint32_t)((rr * W1STR + c * 8) * 2),
             gW1h + rr * 128 + c * 8);
    }
#pragma unroll
    for (int it = 0; it < 2; it++) {               // WH: 512 chunks
        int id = tid + it * TPB;
        int row = id >> 4, c = id & 15;
        cp16(sb + SM_WH + (uint32_t)((row * WHSTR + c * 8) * 2),
             gWHh + row * 128 + c * 8);
    }
    cp_commit();

    // ===== x staging (plain, needs fp32->fp16 convert) =====
#pragma unroll
    for (int it = 0; it < 2; it++) {
        int idx = tid + it * TPB;
        int row = idx >> 2, c = idx & 3;
        const float4* src = reinterpret_cast<const float4*>(
            x + (size_t)(base + row) * INPUT_SZ) + c * 4;
        float4 v0 = __ldg(src), v1 = __ldg(src + 1), v2 = __ldg(src + 2), v3 = __ldg(src + 3);
        uint32_t* dst = reinterpret_cast<uint32_t*>(smem + SM_X + (row * XSTR + c * 16) * 2);
        dst[0] = h2u(v0.x, v0.y); dst[1] = h2u(v0.z, v0.w);
        dst[2] = h2u(v1.x, v1.y); dst[3] = h2u(v1.z, v1.w);
        dst[4] = h2u(v2.x, v2.y); dst[5] = h2u(v2.z, v2.w);
        dst[6] = h2u(v3.x, v3.y); dst[7] = h2u(v3.z, v3.w);
    }
    // biases (tiny, precomputed sums)
    for (int idx = tid; idx < 384; idx += TPB) {
        b0_s[idx] = gB0[idx];
        b1_s[idx] = gB1[idx];
    }
    if (tid < NUM_ACT) bp_s[tid] = gBP[tid];
    if (tid == 0) bv_s[0] = gBV[0];

    cp_wait<1>();          // W0 resident (W1/WH may still be in flight)
    __syncthreads();

    // ================= layer 0: gates = x @ W0^T -> h0 smem =================
#pragma unroll 1
    for (int jq = 0; jq < 2; jq++) {
        float acc[2][3][4][4];
#pragma unroll
        for (int mt = 0; mt < 2; mt++)
#pragma unroll
            for (int g = 0; g < 3; g++)
#pragma unroll
                for (int jt = 0; jt < 4; jt++)
#pragma unroll
                    for (int e = 0; e < 4; e++) acc[mt][g][jt][e] = 0.f;

#pragma unroll 1
        for (int ks = 0; ks < 4; ks++) {
            uint32_t a[2][4];
#pragma unroll
            for (int mt = 0; mt < 2; mt++) {
                uint32_t addr = sb + SM_X +
                    (uint32_t)(((mg * 32 + mt * 16 + rA) * XSTR + ks * 16 + kA) * 2);
                ldsm4(a[mt][0], a[mt][1], a[mt][2], a[mt][3], addr);
            }
#pragma unroll
            for (int g = 0; g < 3; g++) {
#pragma unroll
                for (int jp = 0; jp < 2; jp++) {
                    int jb = jh * 64 + jq * 32 + jp * 16;
                    uint32_t addr = sb + SM_W0 +
                        (uint32_t)(((g * 128 + jb + rB) * W0STR + ks * 16 + kB) * 2);
                    uint32_t b0, b1, b2, b3;
                    ldsm4(b0, b1, b2, b3, addr);
#pragma unroll
                    for (int mt = 0; mt < 2; mt++) {
                        mma16816(acc[mt][g][2 * jp],     a[mt], b0, b1);
                        mma16816(acc[mt][g][2 * jp + 1], a[mt], b2, b3);
                    }
                }
            }
        }
#pragma unroll
        for (int mt = 0; mt < 2; mt++) {
#pragma unroll
            for (int jt = 0; jt < 4; jt++) {
                int j0 = jh * 64 + jq * 32 + jt * 8 + qc;
                float2 bi = *reinterpret_cast<const float2*>(b0_s + j0);
                float2 bg = *reinterpret_cast<const float2*>(b0_s + 128 + j0);
                float2 bo = *reinterpret_cast<const float2*>(b0_s + 256 + j0);
                float v0 = hcell(acc[mt][0][jt][0] + bi.x, acc[mt][1][jt][0] + bg.x,
                                 acc[mt][2][jt][0] + bo.x);
                float v1 = hcell(acc[mt][0][jt][1] + bi.y, acc[mt][1][jt][1] + bg.y,
                                 acc[mt][2][jt][1] + bo.y);
                float v2 = hcell(acc[mt][0][jt][2] + bi.x, acc[mt][1][jt][2] + bg.x,
                                 acc[mt][2][jt][2] + bo.x);
                float v3 = hcell(acc[mt][0][jt][3] + bi.y, acc[mt][1][jt][3] + bg.y,
                                 acc[mt][2][jt][3] + bo.y);
                int ra = mg * 32 + mt * 16 + qr;
                *reinterpret_cast<uint32_t*>(smem + SM_H0 + (ra * HSTR + j0) * 2)
                    = h2u(v0, v1);
                *reinterpret_cast<uint32_t*>(smem + SM_H0 + ((ra + 8) * HSTR + j0) * 2)
                    = h2u(v2, v3);
            }
        }
    }
    cp_wait<0>();          // W1 + WH resident
    __syncthreads();

    // ================= layer 1 + h1 as in-register A-frags =================
    uint32_t hfrag[2][4][4];
#pragma unroll
    for (int jq = 0; jq < 2; jq++) {
        float acc[2][3][4][4];
#pragma unroll
        for (int mt = 0; mt < 2; mt++)
#pragma unroll
            for (int g = 0; g < 3; g++)
#pragma unroll
                for (int jt = 0; jt < 4; jt++)
#pragma unroll
                    for (int e = 0; e < 4; e++) acc[mt][g][jt][e] = 0.f;

#pragma unroll 1
        for (int ks = 0; ks < 8; ks++) {
            uint32_t a[2][4];
#pragma unroll
            for (int mt = 0; mt < 2; mt++) {
                uint32_t addr = sb + SM_H0 +
                    (uint32_t)(((mg * 32 + mt * 16 + rA) * HSTR + ks * 16 + kA) * 2);
                ldsm4(a[mt][0], a[mt][1], a[mt][2], a[mt][3], addr);
            }
#pragma unroll
            for (int g = 0; g < 3; g++) {
#pragma unroll
                for (int jp = 0; jp < 2; jp++) {
                    int jb = jh * 64 + jq * 32 + jp * 16;
                    uint32_t addr = sb + SM_W1 +
                        (uint32_t)(((g * 128 + jb + rB) * W1STR + ks * 16 + kB) * 2);
                    uint32_t b0, b1, b2, b3;
                    ldsm4(b0, b1, b2, b3, addr);
#pragma unroll
                    for (int mt = 0; mt < 2; mt++) {
                        mma16816(acc[mt][g][2 * jp],     a[mt], b0, b1);
                        mma16816(acc[mt][g][2 * jp + 1], a[mt], b2, b3);
                    }
                }
            }
        }
#pragma unroll
        for (int mt = 0; mt < 2; mt++) {
#pragma unroll
            for (int jp = 0; jp < 2; jp++) {
                int kt = jq * 2 + jp;
                float v[2][4];
#pragma unroll
                for (int half = 0; half < 2; half++) {
                    int jt = 2 * jp + half;
                    int j0 = jh * 64 + jq * 32 + jt * 8 + qc;
                    float2 bi = *reinterpret_cast<const float2*>(b1_s + j0);
                    float2 bg = *reinterpret_cast<const float2*>(b1_s + 128 + j0);
                    float2 bo = *reinterpret_cast<const float2*>(b1_s + 256 + j0);
                    v[half][0] = hcell(acc[mt][0][jt][0] + bi.x, acc[mt][1][jt][0] + bg.x,
                                       acc[mt][2][jt][0] + bo.x);
                    v[half][1] = hcell(acc[mt][0][jt][1] + bi.y, acc[mt][1][jt][1] + bg.y,
                                       acc[mt][2][jt][1] + bo.y);
                    v[half][2] = hcell(acc[mt][0][jt][2] + bi.x, acc[mt][1][jt][2] + bg.x,
                                       acc[mt][2][jt][2] + bo.x);
                    v[half][3] = hcell(acc[mt][0][jt][3] + bi.y, acc[mt][1][jt][3] + bg.y,
                                       acc[mt][2][jt][3] + bo.y);
                }
                hfrag[mt][kt][0] = h2u(v[0][0], v[0][1]);
                hfrag[mt][kt][1] = h2u(v[0][2], v[0][3]);
                hfrag[mt][kt][2] = h2u(v[1][0], v[1][1]);
                hfrag[mt][kt][3] = h2u(v[1][2], v[1][3]);
            }
        }
    }

    // ================= heads: [m x 17] = h1 @ WH^T =================
    float hacc[2][3][4];
#pragma unroll
    for (int mt = 0; mt < 2; mt++)
#pragma unroll
        for (int nt = 0; nt < 3; nt++)
#pragma unroll
            for (int e = 0; e < 4; e++) hacc[mt][nt][e] = 0.f;

#pragma unroll
    for (int kt = 0; kt < 4; kt++) {
        int kg = jh * 64 + kt * 16;
        uint32_t b0, b1, b2, b3, c0, c1;
        uint32_t addr01 = sb + SM_WH + (uint32_t)(((rB) * WHSTR + kg + kB) * 2);
        ldsm4(b0, b1, b2, b3, addr01);
        uint32_t addr2 = sb + SM_WH +
            (uint32_t)(((16 + (lane & 7)) * WHSTR + kg + ((lane >> 3) & 1) * 8) * 2);
        ldsm2(c0, c1, addr2);
#pragma unroll
        for (int mt = 0; mt < 2; mt++) {
            mma16816(hacc[mt][0], hfrag[mt][kt], b0, b1);
            mma16816(hacc[mt][1], hfrag[mt][kt], b2, b3);
            mma16816(hacc[mt][2], hfrag[mt][kt], c0, c1);
        }
    }

    // ================= cross-warp (j-half) reduction + writeout =============
    float* buf = reinterpret_cast<float*>(smem + SM_BUF);
    if (jh == 0) {
#pragma unroll
        for (int mt = 0; mt < 2; mt++)
#pragma unroll
            for (int nt = 0; nt < 3; nt++)
#pragma unroll
                for (int e = 0; e < 4; e++) {
                    int n = nt * 8 + qc + (e & 1);
                    if (n < 17) {
                        int m = mg * 32 + mt * 16 + qr + ((e >= 2) ? 8 : 0);
                        buf[m * BUFSTR + n] = hacc[mt][nt][e];
                    }
                }
    }
    __syncthreads();
    if (jh == 1) {
#pragma unroll
        for (int mt = 0; mt < 2; mt++)
#pragma unroll
            for (int nt = 0; nt < 3; nt++)
#pragma unroll
                for (int e = 0; e < 4; e++) {
                    int n = nt * 8 + qc + (e & 1);
                    if (n < 17) {
                        int m = mg * 32 + mt * 16 + qr + ((e >= 2) ? 8 : 0);
                        buf[m * BUFSTR + n] += hacc[mt][nt][e];
                    }
                }
    }
    __syncthreads();

    {
        int row = tid >> 1, hn = tid & 1;
        const float* src = buf + row * BUFSTR + hn * 8;
        float4 o0 = make_float4(src[0] + bp_s[hn * 8 + 0], src[1] + bp_s[hn * 8 + 1],
                                src[2] + bp_s[hn * 8 + 2], src[3] + bp_s[hn * 8 + 3]);
        float4 o1 = make_float4(src[4] + bp_s[hn * 8 + 4], src[5] + bp_s[hn * 8 + 5],
                                src[6] + bp_s[hn * 8 + 6], src[7] + bp_s[hn * 8 + 7]);
        float4* dst = reinterpret_cast<float4*>(
            out_policy + (size_t)(base + row) * NUM_ACT + hn * 8);
        dst[0] = o0; dst[1] = o1;
        if (tid < BM)
            out_value[base + tid] = buf[tid * BUFSTR + 16] + bv_s[0];
    }
}

extern "C" void kernel_launch(void* const* d_in, const int* in_sizes, int n_in,
                              void* d_out, int out_size)
{
    (void)in_sizes; (void)n_in; (void)out_size;
    // 0:x 1:Wih0 2:Whh0(dead) 3:bih0 4:bhh0 5:Wih1 6:Whh1(dead) 7:bih1 8:bhh1
    // 9:Wp 10:bp 11:Wv 12:bv
    const float* x    = (const float*)d_in[0];
    const float* Wih0 = (const float*)d_in[1];
    const float* bih0 = (const float*)d_in[3];
    const float* bhh0 = (const float*)d_in[4];
    const float* Wih1 = (const float*)d_in[5];
    const float* bih1 = (const float*)d_in[7];
    const float* bhh1 = (const float*)d_in[8];
    const float* Wp   = (const float*)d_in[9];
    const float* bp   = (const float*)d_in[10];
    const float* Wv   = (const float*)d_in[11];
    const float* bv   = (const float*)d_in[12];

    float* out        = (float*)d_out;
    float* out_policy = out;
    float* out_value  = out + (size_t)BATCH_N * NUM_ACT;

    prep_weights<<<64, 256>>>(Wih0, Wih1, Wp, Wv, bih0, bhh0, bih1, bhh1, bp, bv);

    cudaFuncSetAttribute((const void*)lstm_policy_mma,
                         cudaFuncAttributeMaxDynamicSharedMemorySize, SM_TOTAL);
    lstm_policy_mma<<<BATCH_N / BM, TPB, SM_TOTAL>>>(x, out_policy, out_value);
}

// round 8
// speedup vs baseline: 10.5527x; 1.0153x over previous
#include <cuda_runtime.h>
#include <cuda_fp16.h>
#include <cstdint>
#include <math.h>

#define HIDDEN    128
#define INPUT_SZ  64
#define NUM_ACT   16
#define BATCH_N   65536
#define TPB       512
#define BM        128

// padded strides (in halfs) -> conflict-free ldmatrix
#define XSTR   72
#define W0STR  72
#define W1STR  136
#define WHSTR  136
#define HSTR   136
#define BUFSTR 20

// smem layout (bytes)
#define SM_X    0                      // 128*72*2   = 18432
#define SM_BUF  0                      // [4][128][20] f32 = 40960 (aliases X+W0 head; both dead)
#define SM_W0   18432                  // 3*128*72*2 = 55296
#define SM_W1   73728                  // 3*128*136*2= 104448
#define SM_WH   178176                 // 32*136*2   = 8704
#define SM_H0   186880                 // 128*136*2  = 34816
#define SM_B0   221696
#define SM_B1   223232
#define SM_BP   224768
#define SM_BV   224832
#define SM_TOTAL 224896

// ---------------- precomputed fp16 weights / f32 bias sums (device globals) --
__device__ __half gW0h[3 * 128 * 64];     // [g*128+j][64]
__device__ __half gW1h[3 * 128 * 128];    // [g*128+j][128]
__device__ __half gWHh[32 * 128];         // rows 0-15 Wp, 16 Wv, 17-31 zero
__device__ float  gB0[384], gB1[384], gBP[16], gBV[1];

__device__ __forceinline__ uint32_t smem_u32(const void* p) {
    uint32_t a;
    asm("{ .reg .u64 t; cvta.to.shared.u64 t, %1; cvt.u32.u64 %0, t; }"
        : "=r"(a) : "l"(p));
    return a;
}
__device__ __forceinline__ void cp16(uint32_t dst, const void* src) {
    asm volatile("cp.async.cg.shared.global [%0], [%1], 16;"
                 :: "r"(dst), "l"(src));
}
__device__ __forceinline__ void cp_commit() {
    asm volatile("cp.async.commit_group;" ::: "memory");
}
template <int N>
__device__ __forceinline__ void cp_wait() {
    asm volatile("cp.async.wait_group %0;" :: "n"(N) : "memory");
}
__device__ __forceinline__ void ldsm4(uint32_t& r0, uint32_t& r1, uint32_t& r2,
                                      uint32_t& r3, uint32_t addr) {
    asm volatile("ldmatrix.sync.aligned.m8n8.x4.shared.b16 {%0,%1,%2,%3}, [%4];"
                 : "=r"(r0), "=r"(r1), "=r"(r2), "=r"(r3) : "r"(addr));
}
__device__ __forceinline__ void ldsm2(uint32_t& r0, uint32_t& r1, uint32_t addr) {
    asm volatile("ldmatrix.sync.aligned.m8n8.x2.shared.b16 {%0,%1}, [%2];"
                 : "=r"(r0), "=r"(r1) : "r"(addr));
}
__device__ __forceinline__ void mma16816(float* d, const uint32_t* a,
                                         uint32_t b0, uint32_t b1) {
    asm volatile(
        "mma.sync.aligned.m16n8k16.row.col.f32.f16.f16.f32 "
        "{%0,%1,%2,%3}, {%4,%5,%6,%7}, {%8,%9}, {%0,%1,%2,%3};"
        : "+f"(d[0]), "+f"(d[1]), "+f"(d[2]), "+f"(d[3])
        : "r"(a[0]), "r"(a[1]), "r"(a[2]), "r"(a[3]), "r"(b0), "r"(b1));
}

// 6-MUFU hcell: sig(i)*tanh(g) = (2-B)/(A*B); h = (1-F)*rcp((1+F)*D)
__device__ __forceinline__ float hcell(float i, float g, float o) {
    i = fmaxf(i, -30.0f); g = fmaxf(g, -15.0f); o = fmaxf(o, -30.0f);
    float A = 1.0f + __expf(-i);
    float B = 1.0f + __expf(-2.0f * g);
    float c = (2.0f - B) * __fdividef(1.0f, A * B);   // sig(i)*tanh(g), in (-1,1)
    float F = __expf(-2.0f * c);
    float D = 1.0f + __expf(-o);
    return (1.0f - F) * __fdividef(1.0f, (1.0f + F) * D);
}
__device__ __forceinline__ int grow_of(int g) {   // live gates i,g,o in 4H blocks
    return (g == 0) ? 0 : (g == 1) ? 2 * HIDDEN : 3 * HIDDEN;
}
__device__ __forceinline__ uint32_t h2u(float a, float b) {
    __half2 h = __floats2half2_rn(a, b);
    return *reinterpret_cast<uint32_t*>(&h);
}

// =================== prep kernel: fp32 -> fp16 weights, bias sums ============
extern "C" __global__ void prep_weights(const float* __restrict__ Wih0,
                                        const float* __restrict__ Wih1,
                                        const float* __restrict__ Wp,
                                        const float* __restrict__ Wv,
                                        const float* __restrict__ bih0,
                                        const float* __restrict__ bhh0,
                                        const float* __restrict__ bih1,
                                        const float* __restrict__ bhh1,
                                        const float* __restrict__ bp,
                                        const float* __restrict__ bv)
{
    const int tid = blockIdx.x * blockDim.x + threadIdx.x;
    const int nt  = gridDim.x * blockDim.x;
    for (int idx = tid; idx < 3 * 128 * 64; idx += nt) {
        int rr = idx >> 6, c = idx & 63;
        int g = rr >> 7, j = rr & 127;
        gW0h[idx] = __float2half_rn(__ldg(Wih0 + (size_t)(grow_of(g) + j) * 64 + c));
    }
    for (int idx = tid; idx < 3 * 128 * 128; idx += nt) {
        int rr = idx >> 7, c = idx & 127;
        int g = rr >> 7, j = rr & 127;
        gW1h[idx] = __float2half_rn(__ldg(Wih1 + (size_t)(grow_of(g) + j) * 128 + c));
    }
    for (int idx = tid; idx < 32 * 128; idx += nt) {
        int row = idx >> 7, c = idx & 127;
        float v = (row < NUM_ACT) ? __ldg(Wp + row * 128 + c)
                : (row == NUM_ACT) ? __ldg(Wv + c) : 0.0f;
        gWHh[idx] = __float2half_rn(v);
    }
    for (int idx = tid; idx < 384; idx += nt) {
        int g = idx >> 7, j = idx & 127;
        int row = grow_of(g) + j;
        gB0[idx] = __ldg(bih0 + row) + __ldg(bhh0 + row);
        gB1[idx] = __ldg(bih1 + row) + __ldg(bhh1 + row);
    }
    if (tid < NUM_ACT) gBP[tid] = __ldg(bp + tid);
    if (tid == 0) gBV[0] = __ldg(bv);
}

// =================== main kernel: 16 warps = 4 m-groups x 4 j-quarters =======
extern "C" __global__ void __launch_bounds__(TPB, 1)
lstm_policy_mma(const float* __restrict__ x,
                float* __restrict__ out_policy,
                float* __restrict__ out_value)
{
    extern __shared__ char smem[];
    const uint32_t sb = smem_u32(smem);
    const int tid  = threadIdx.x;
    const int lane = tid & 31;
    const int wid  = tid >> 5;
    const int mg   = wid >> 2;         // 0..3 : 32-row m-group
    const int jqw  = wid & 3;          // 0..3 : 32-col j-quarter
    const int base = blockIdx.x * BM;

    float* b0_s = reinterpret_cast<float*>(smem + SM_B0);
    float* b1_s = reinterpret_cast<float*>(smem + SM_B1);
    float* bp_s = reinterpret_cast<float*>(smem + SM_BP);
    float* bv_s = reinterpret_cast<float*>(smem + SM_BV);

    const int rA   = lane & 15;
    const int kA   = ((lane >> 4) & 1) * 8;
    const int rB   = (lane & 7) + ((lane >> 4) & 1) * 8;
    const int kB   = ((lane >> 3) & 1) * 8;
    const int qr   = lane >> 2;
    const int qc   = (lane & 3) * 2;

    // ===== async staging: group A = W0, group B = W1 + WH (fp16 copies) =====
#pragma unroll
    for (int it = 0; it < 6; it++) {               // W0: 3072 16B chunks
        int id = tid + it * TPB;
        int rr = id >> 3, c = id & 7;
        cp16(sb + SM_W0 + (uint32_t)((rr * W0STR + c * 8) * 2),
             gW0h + rr * 64 + c * 8);
    }
    cp_commit();
#pragma unroll
    for (int it = 0; it < 12; it++) {              // W1: 6144 chunks
        int id = tid + it * TPB;
        int rr = id >> 4, c = id & 15;
        cp16(sb + SM_W1 + (uint32_t)((rr * W1STR + c * 8) * 2),
             gW1h + rr * 128 + c * 8);
    }
    {                                              // WH: 512 chunks
        int row = tid >> 4, c = tid & 15;
        cp16(sb + SM_WH + (uint32_t)((row * WHSTR + c * 8) * 2),
             gWHh + row * 128 + c * 8);
    }
    cp_commit();

    // ===== x staging (fp32->fp16 convert) =====
    {
        int row = tid >> 2, c = tid & 3;           // 512 slots
        const float4* src = reinterpret_cast<const float4*>(
            x + (size_t)(base + row) * INPUT_SZ) + c * 4;
        float4 v0 = __ldg(src), v1 = __ldg(src + 1), v2 = __ldg(src + 2), v3 = __ldg(src + 3);
        uint32_t* dst = reinterpret_cast<uint32_t*>(smem + SM_X + (row * XSTR + c * 16) * 2);
        dst[0] = h2u(v0.x, v0.y); dst[1] = h2u(v0.z, v0.w);
        dst[2] = h2u(v1.x, v1.y); dst[3] = h2u(v1.z, v1.w);
        dst[4] = h2u(v2.x, v2.y); dst[5] = h2u(v2.z, v2.w);
        dst[6] = h2u(v3.x, v3.y); dst[7] = h2u(v3.z, v3.w);
    }
    // biases (tiny, precomputed sums)
    if (tid < 384) {
        b0_s[tid] = gB0[tid];
        b1_s[tid] = gB1[tid];
    }
    if (tid < NUM_ACT) bp_s[tid] = gBP[tid];
    if (tid == 0) bv_s[0] = gBV[0];

    cp_wait<1>();          // W0 resident (W1/WH may still be in flight)
    __syncthreads();

    // ================= layer 0: gates = x @ W0^T -> h0 smem =================
    {
        float acc[2][3][4][4];
#pragma unroll
        for (int mt = 0; mt < 2; mt++)
#pragma unroll
            for (int g = 0; g < 3; g++)
#pragma unroll
                for (int jt = 0; jt < 4; jt++)
#pragma unroll
                    for (int e = 0; e < 4; e++) acc[mt][g][jt][e] = 0.f;

#pragma unroll 1
        for (int ks = 0; ks < 4; ks++) {
            uint32_t a[2][4];
#pragma unroll
            for (int mt = 0; mt < 2; mt++) {
                uint32_t addr = sb + SM_X +
                    (uint32_t)(((mg * 32 + mt * 16 + rA) * XSTR + ks * 16 + kA) * 2);
                ldsm4(a[mt][0], a[mt][1], a[mt][2], a[mt][3], addr);
            }
#pragma unroll
            for (int g = 0; g < 3; g++) {
#pragma unroll
                for (int jp = 0; jp < 2; jp++) {
                    int jb = jqw * 32 + jp * 16;
                    uint32_t addr = sb + SM_W0 +
                        (uint32_t)(((g * 128 + jb + rB) * W0STR + ks * 16 + kB) * 2);
                    uint32_t b0, b1, b2, b3;
                    ldsm4(b0, b1, b2, b3, addr);
#pragma unroll
                    for (int mt = 0; mt < 2; mt++) {
                        mma16816(acc[mt][g][2 * jp],     a[mt], b0, b1);
                        mma16816(acc[mt][g][2 * jp + 1], a[mt], b2, b3);
                    }
                }
            }
        }
#pragma unroll
        for (int mt = 0; mt < 2; mt++) {
#pragma unroll
            for (int jt = 0; jt < 4; jt++) {
                int j0 = jqw * 32 + jt * 8 + qc;
                float2 bi = *reinterpret_cast<const float2*>(b0_s + j0);
                float2 bg = *reinterpret_cast<const float2*>(b0_s + 128 + j0);
                float2 bo = *reinterpret_cast<const float2*>(b0_s + 256 + j0);
                float v0 = hcell(acc[mt][0][jt][0] + bi.x, acc[mt][1][jt][0] + bg.x,
                                 acc[mt][2][jt][0] + bo.x);
                float v1 = hcell(acc[mt][0][jt][1] + bi.y, acc[mt][1][jt][1] + bg.y,
                                 acc[mt][2][jt][1] + bo.y);
                float v2 = hcell(acc[mt][0][jt][2] + bi.x, acc[mt][1][jt][2] + bg.x,
                                 acc[mt][2][jt][2] + bo.x);
                float v3 = hcell(acc[mt][0][jt][3] + bi.y, acc[mt][1][jt][3] + bg.y,
                                 acc[mt][2][jt][3] + bo.y);
                int ra = mg * 32 + mt * 16 + qr;
                *reinterpret_cast<uint32_t*>(smem + SM_H0 + (ra * HSTR + j0) * 2)
                    = h2u(v0, v1);
                *reinterpret_cast<uint32_t*>(smem + SM_H0 + ((ra + 8) * HSTR + j0) * 2)
                    = h2u(v2, v3);
            }
        }
    }
    cp_wait<0>();          // W1 + WH resident
    __syncthreads();

    // ================= layer 1 + h1 as in-register A-frags =================
    uint32_t hfrag[2][2][4];   // [mt][kt-in-quarter][4]
    {
        float acc[2][3][4][4];
#pragma unroll
        for (int mt = 0; mt < 2; mt++)
#pragma unroll
            for (int g = 0; g < 3; g++)
#pragma unroll
                for (int jt = 0; jt < 4; jt++)
#pragma unroll
                    for (int e = 0; e < 4; e++) acc[mt][g][jt][e] = 0.f;

#pragma unroll 1
        for (int ks = 0; ks < 8; ks++) {
            uint32_t a[2][4];
#pragma unroll
            for (int mt = 0; mt < 2; mt++) {
                uint32_t addr = sb + SM_H0 +
                    (uint32_t)(((mg * 32 + mt * 16 + rA) * HSTR + ks * 16 + kA) * 2);
                ldsm4(a[mt][0], a[mt][1], a[mt][2], a[mt][3], addr);
            }
#pragma unroll
            for (int g = 0; g < 3; g++) {
#pragma unroll
                for (int jp = 0; jp < 2; jp++) {
                    int jb = jqw * 32 + jp * 16;
                    uint32_t addr = sb + SM_W1 +
                        (uint32_t)(((g * 128 + jb + rB) * W1STR + ks * 16 + kB) * 2);
                    uint32_t b0, b1, b2, b3;
                    ldsm4(b0, b1, b2, b3, addr);
#pragma unroll
                    for (int mt = 0; mt < 2; mt++) {
                        mma16816(acc[mt][g][2 * jp],     a[mt], b0, b1);
                        mma16816(acc[mt][g][2 * jp + 1], a[mt], b2, b3);
                    }
                }
            }
        }
        // epilogue: hcell -> packed A-fragments (kt = jp, k = jqw*32 + kt*16)
#pragma unroll
        for (int mt = 0; mt < 2; mt++) {
#pragma unroll
            for (int jp = 0; jp < 2; jp++) {
                float v[2][4];
#pragma unroll
                for (int half = 0; half < 2; half++) {
                    int jt = 2 * jp + half;
                    int j0 = jqw * 32 + jt * 8 + qc;
                    float2 bi = *reinterpret_cast<const float2*>(b1_s + j0);
                    float2 bg = *reinterpret_cast<const float2*>(b1_s + 128 + j0);
                    float2 bo = *reinterpret_cast<const float2*>(b1_s + 256 + j0);
                    v[half][0] = hcell(acc[mt][0][jt][0] + bi.x, acc[mt][1][jt][0] + bg.x,
                                       acc[mt][2][jt][0] + bo.x);
                    v[half][1] = hcell(acc[mt][0][jt][1] + bi.y, acc[mt][1][jt][1] + bg.y,
                                       acc[mt][2][jt][1] + bo.y);
                    v[half][2] = hcell(acc[mt][0][jt][2] + bi.x, acc[mt][1][jt][2] + bg.x,
                                       acc[mt][2][jt][2] + bo.x);
                    v[half][3] = hcell(acc[mt][0][jt][3] + bi.y, acc[mt][1][jt][3] + bg.y,
                                       acc[mt][2][jt][3] + bo.y);
                }
                hfrag[mt][jp][0] = h2u(v[0][0], v[0][1]);
                hfrag[mt][jp][1] = h2u(v[0][2], v[0][3]);
                hfrag[mt][jp][2] = h2u(v[1][0], v[1][1]);
                hfrag[mt][jp][3] = h2u(v[1][2], v[1][3]);
            }
        }
    }

    // ================= heads: partial [m x 17] over this warp's 32-k chunk ===
    float hacc[2][3][4];
#pragma unroll
    for (int mt = 0; mt < 2; mt++)
#pragma unroll
        for (int nt = 0; nt < 3; nt++)
#pragma unroll
            for (int e = 0; e < 4; e++) hacc[mt][nt][e] = 0.f;

#pragma unroll
    for (int kt = 0; kt < 2; kt++) {
        int kg = jqw * 32 + kt * 16;
        uint32_t b0, b1, b2, b3, c0, c1;
        uint32_t addr01 = sb + SM_WH + (uint32_t)(((rB) * WHSTR + kg + kB) * 2);
        ldsm4(b0, b1, b2, b3, addr01);
        uint32_t addr2 = sb + SM_WH +
            (uint32_t)(((16 + (lane & 7)) * WHSTR + kg + ((lane >> 3) & 1) * 8) * 2);
        ldsm2(c0, c1, addr2);
#pragma unroll
        for (int mt = 0; mt < 2; mt++) {
            mma16816(hacc[mt][0], hfrag[mt][kt], b0, b1);
            mma16816(hacc[mt][1], hfrag[mt][kt], b2, b3);
            mma16816(hacc[mt][2], hfrag[mt][kt], c0, c1);
        }
    }

    // ================= 4-way cross-warp (j-quarter) reduction ================
    __syncthreads();       // X/W0 regions now dead -> BUF alias safe
    float* buf = reinterpret_cast<float*>(smem + SM_BUF);
#pragma unroll
    for (int mt = 0; mt < 2; mt++)
#pragma unroll
        for (int nt = 0; nt < 3; nt++)
#pragma unroll
            for (int e = 0; e < 4; e++) {
                int n = nt * 8 + qc + (e & 1);
                if (n < 17) {
                    int m = mg * 32 + mt * 16 + qr + ((e >= 2) ? 8 : 0);
                    buf[(jqw * BM + m) * BUFSTR + n] = hacc[mt][nt][e];
                }
            }
    __syncthreads();

    if (tid < 2 * BM) {
        int row = tid >> 1, hn = tid & 1;
        float s[8];
#pragma unroll
        for (int c = 0; c < 8; c++) s[c] = bp_s[hn * 8 + c];
#pragma unroll
        for (int q = 0; q < 4; q++) {
            const float* src = buf + (q * BM + row) * BUFSTR + hn * 8;
#pragma unroll
            for (int c = 0; c < 8; c++) s[c] += src[c];
        }
        float4* dst = reinterpret_cast<float4*>(
            out_policy + (size_t)(base + row) * NUM_ACT + hn * 8);
        dst[0] = make_float4(s[0], s[1], s[2], s[3]);
        dst[1] = make_float4(s[4], s[5], s[6], s[7]);
    } else if (tid < 3 * BM) {
        int row = tid - 2 * BM;
        float v = bv_s[0];
#pragma unroll
        for (int q = 0; q < 4; q++) v += buf[(q * BM + row) * BUFSTR + 16];
        out_value[base + row] = v;
    }
}

extern "C" void kernel_launch(void* const* d_in, const int* in_sizes, int n_in,
                              void* d_out, int out_size)
{
    (void)in_sizes; (void)n_in; (void)out_size;
    // 0:x 1:Wih0 2:Whh0(dead) 3:bih0 4:bhh0 5:Wih1 6:Whh1(dead) 7:bih1 8:bhh1
    // 9:Wp 10:bp 11:Wv 12:bv
    const float* x    = (const float*)d_in[0];
    const float* Wih0 = (const float*)d_in[1];
    const float* bih0 = (const float*)d_in[3];
    const float* bhh0 = (const float*)d_in[4];
    const float* Wih1 = (const float*)d_in[5];
    const float* bih1 = (const float*)d_in[7];
    const float* bhh1 = (const float*)d_in[8];
    const float* Wp   = (const float*)d_in[9];
    const float* bp   = (const float*)d_in[10];
    const float* Wv   = (const float*)d_in[11];
    const float* bv   = (const float*)d_in[12];

    float* out        = (float*)d_out;
    float* out_policy = out;
    float* out_value  = out + (size_t)BATCH_N * NUM_ACT;

    prep_weights<<<64, 256>>>(Wih0, Wih1, Wp, Wv, bih0, bhh0, bih1, bhh1, bp, bv);

    cudaFuncSetAttribute((const void*)lstm_policy_mma,
                         cudaFuncAttributeMaxDynamicSharedMemorySize, SM_TOTAL);
    lstm_policy_mma<<<BATCH_N / BM, TPB, SM_TOTAL>>>(x, out_policy, out_value);
}

// round 10
// speedup vs baseline: 11.6657x; 1.1055x over previous
#include <cuda_runtime.h>
#include <cuda_fp16.h>
#include <cstdint>
#include <math.h>

#define HIDDEN    128
#define INPUT_SZ  64
#define NUM_ACT   16
#define BATCH_N   65536
#define TPB       512
#define BM        128
#define NTILES    (BATCH_N / BM)      // 512
#define NCTA      148

// padded strides (in halfs) -> conflict-free ldmatrix
#define XSTR   72
#define W0STR  72
#define W1STR  136
#define WHSTR  136
#define HSTR   136
#define BUFSTR 17                      // exact-fit head reduce buffer (floats)

// smem layout (bytes)
#define SM_X    0                      // 128*72*2   = 18432 (live every tile: prefetch target)
#define SM_W0   18432                  // 3*128*72*2 = 55296
#define SM_W1   73728                  // 3*128*136*2= 104448
#define SM_WH   178176                 // 32*136*2   = 8704
#define SM_H0   186880                 // 128*136*2  = 34816
#define SM_BUF  186880                 // [4][128][17] f32 = 34812 (aliases H0, dead at reduce)
#define SM_B0   221696
#define SM_B1   223232
#define SM_BP   224768
#define SM_BV   224832
#define SM_TOTAL 224896

// ---------------- precomputed fp16 tensors / f32 bias sums (device globals) --
__device__ __half gW0h[3 * 128 * 64];     // [g*128+j][64]
__device__ __half gW1h[3 * 128 * 128];    // [g*128+j][128]
__device__ __half gWHh[32 * 128];         // rows 0-15 Wp, 16 Wv, 17-31 zero
__device__ __half gXh[BATCH_N * INPUT_SZ];// x pre-converted to fp16
__device__ float  gB0[384], gB1[384], gBP[16], gBV[1];

__device__ __forceinline__ uint32_t smem_u32(const void* p) {
    uint32_t a;
    asm("{ .reg .u64 t; cvta.to.shared.u64 t, %1; cvt.u32.u64 %0, t; }"
        : "=r"(a) : "l"(p));
    return a;
}
__device__ __forceinline__ void cp16(uint32_t dst, const void* src) {
    asm volatile("cp.async.cg.shared.global [%0], [%1], 16;"
                 :: "r"(dst), "l"(src));
}
__device__ __forceinline__ void cp_commit() {
    asm volatile("cp.async.commit_group;" ::: "memory");
}
template <int N>
__device__ __forceinline__ void cp_wait() {
    asm volatile("cp.async.wait_group %0;" :: "n"(N) : "memory");
}
__device__ __forceinline__ void ldsm4(uint32_t& r0, uint32_t& r1, uint32_t& r2,
                                      uint32_t& r3, uint32_t addr) {
    asm volatile("ldmatrix.sync.aligned.m8n8.x4.shared.b16 {%0,%1,%2,%3}, [%4];"
                 : "=r"(r0), "=r"(r1), "=r"(r2), "=r"(r3) : "r"(addr));
}
__device__ __forceinline__ void ldsm2(uint32_t& r0, uint32_t& r1, uint32_t addr) {
    asm volatile("ldmatrix.sync.aligned.m8n8.x2.shared.b16 {%0,%1}, [%2];"
                 : "=r"(r0), "=r"(r1) : "r"(addr));
}
__device__ __forceinline__ void mma16816(float* d, const uint32_t* a,
                                         uint32_t b0, uint32_t b1) {
    asm volatile(
        "mma.sync.aligned.m16n8k16.row.col.f32.f16.f16.f32 "
        "{%0,%1,%2,%3}, {%4,%5,%6,%7}, {%8,%9}, {%0,%1,%2,%3};"
        : "+f"(d[0]), "+f"(d[1]), "+f"(d[2]), "+f"(d[3])
        : "r"(a[0]), "r"(a[1]), "r"(a[2]), "r"(a[3]), "r"(b0), "r"(b1));
}

// 6-MUFU hcell: sig(i)*tanh(g) = (2-B)/(A*B); h = (1-F)*rcp((1+F)*D)
__device__ __forceinline__ float hcell(float i, float g, float o) {
    i = fmaxf(i, -30.0f); g = fmaxf(g, -15.0f); o = fmaxf(o, -30.0f);
    float A = 1.0f + __expf(-i);
    float B = 1.0f + __expf(-2.0f * g);
    float c = (2.0f - B) * __fdividef(1.0f, A * B);   // sig(i)*tanh(g), in (-1,1)
    float F = __expf(-2.0f * c);
    float D = 1.0f + __expf(-o);
    return (1.0f - F) * __fdividef(1.0f, (1.0f + F) * D);
}
__device__ __forceinline__ int grow_of(int g) {   // live gates i,g,o in 4H blocks
    return (g == 0) ? 0 : (g == 1) ? 2 * HIDDEN : 3 * HIDDEN;
}
__device__ __forceinline__ uint32_t h2u(float a, float b) {
    __half2 h = __floats2half2_rn(a, b);
    return *reinterpret_cast<uint32_t*>(&h);
}

// =================== prep kernel: fp32 -> fp16 weights + x, bias sums ========
extern "C" __global__ void prep_weights(const float* __restrict__ x,
                                        const float* __restrict__ Wih0,
                                        const float* __restrict__ Wih1,
                                        const float* __restrict__ Wp,
                                        const float* __restrict__ Wv,
                                        const float* __restrict__ bih0,
                                        const float* __restrict__ bhh0,
                                        const float* __restrict__ bih1,
                                        const float* __restrict__ bhh1,
                                        const float* __restrict__ bp,
                                        const float* __restrict__ bv)
{
    const int tid = blockIdx.x * blockDim.x + threadIdx.x;
    const int nt  = gridDim.x * blockDim.x;
    // x: 65536*64 fp32 -> fp16, 8 floats per step (vectorized)
    const int NX8 = BATCH_N * INPUT_SZ / 8;
    for (int idx = tid; idx < NX8; idx += nt) {
        const float4* src = reinterpret_cast<const float4*>(x) + 2 * idx;
        float4 a = __ldg(src), b = __ldg(src + 1);
        uint4 u = make_uint4(h2u(a.x, a.y), h2u(a.z, a.w), h2u(b.x, b.y), h2u(b.z, b.w));
        *(reinterpret_cast<uint4*>(gXh) + idx) = u;
    }
    for (int idx = tid; idx < 3 * 128 * 64; idx += nt) {
        int rr = idx >> 6, c = idx & 63;
        int g = rr >> 7, j = rr & 127;
        gW0h[idx] = __float2half_rn(__ldg(Wih0 + (size_t)(grow_of(g) + j) * 64 + c));
    }
    for (int idx = tid; idx < 3 * 128 * 128; idx += nt) {
        int rr = idx >> 7, c = idx & 127;
        int g = rr >> 7, j = rr & 127;
        gW1h[idx] = __float2half_rn(__ldg(Wih1 + (size_t)(grow_of(g) + j) * 128 + c));
    }
    for (int idx = tid; idx < 32 * 128; idx += nt) {
        int row = idx >> 7, c = idx & 127;
        float v = (row < NUM_ACT) ? __ldg(Wp + row * 128 + c)
                : (row == NUM_ACT) ? __ldg(Wv + c) : 0.0f;
        gWHh[idx] = __float2half_rn(v);
    }
    for (int idx = tid; idx < 384; idx += nt) {
        int g = idx >> 7, j = idx & 127;
        int row = grow_of(g) + j;
        gB0[idx] = __ldg(bih0 + row) + __ldg(bhh0 + row);
        gB1[idx] = __ldg(bih1 + row) + __ldg(bhh1 + row);
    }
    if (tid < NUM_ACT) gBP[tid] = __ldg(bp + tid);
    if (tid == 0) gBV[0] = __ldg(bv);
}

// x tile -> smem via cp.async (1024 16B chunks; 2 per thread)
__device__ __forceinline__ void stage_x(uint32_t sb, int tile, int tid) {
    const __half* src0 = gXh + (size_t)tile * BM * INPUT_SZ;
#pragma unroll
    for (int it = 0; it < 2; it++) {
        int id = tid + it * TPB;
        int row = id >> 3, c = id & 7;
        cp16(sb + SM_X + (uint32_t)((row * XSTR + c * 8) * 2),
             src0 + row * INPUT_SZ + c * 8);
    }
}

// =================== main persistent kernel ==================================
extern "C" __global__ void __launch_bounds__(TPB, 1)
lstm_policy_mma(float* __restrict__ out_policy,
                float* __restrict__ out_value)
{
    extern __shared__ char smem[];
    const uint32_t sb = smem_u32(smem);
    const int tid  = threadIdx.x;
    const int lane = tid & 31;
    const int wid  = tid >> 5;
    const int mg   = wid >> 2;         // 0..3 : 32-row m-group
    const int jqw  = wid & 3;          // 0..3 : 32-col j-quarter

    float* b0_s = reinterpret_cast<float*>(smem + SM_B0);
    float* b1_s = reinterpret_cast<float*>(smem + SM_B1);
    float* bp_s = reinterpret_cast<float*>(smem + SM_BP);
    float* bv_s = reinterpret_cast<float*>(smem + SM_BV);

    const int rA   = lane & 15;
    const int kA   = ((lane >> 4) & 1) * 8;
    const int rB   = (lane & 7) + ((lane >> 4) & 1) * 8;
    const int kB   = ((lane >> 3) & 1) * 8;
    const int qr   = lane >> 2;
    const int qc   = (lane & 3) * 2;

    // ===== prologue: group A = W0 + x(first tile); group B = W1 + WH =====
#pragma unroll
    for (int it = 0; it < 6; it++) {               // W0: 3072 16B chunks
        int id = tid + it * TPB;
        int rr = id >> 3, c = id & 7;
        cp16(sb + SM_W0 + (uint32_t)((rr * W0STR + c * 8) * 2),
             gW0h + rr * 64 + c * 8);
    }
    stage_x(sb, blockIdx.x, tid);
    cp_commit();                                   // group A
#pragma unroll
    for (int it = 0; it < 12; it++) {              // W1: 6144 chunks
        int id = tid + it * TPB;
        int rr = id >> 4, c = id & 15;
        cp16(sb + SM_W1 + (uint32_t)((rr * W1STR + c * 8) * 2),
             gW1h + rr * 128 + c * 8);
    }
    {                                              // WH: 512 chunks
        int row = tid >> 4, c = tid & 15;
        cp16(sb + SM_WH + (uint32_t)((row * WHSTR + c * 8) * 2),
             gWHh + row * 128 + c * 8);
    }
    cp_commit();                                   // group B

    // biases (tiny, precomputed sums)
    if (tid < 384) {
        b0_s[tid] = gB0[tid];
        b1_s[tid] = gB1[tid];
    }
    if (tid < NUM_ACT) bp_s[tid] = gBP[tid];
    if (tid == 0) bv_s[0] = gBV[0];

    cp_wait<1>();          // group A done: W0 + x0 resident
    __syncthreads();

    // =================== persistent tile loop ===================
    for (int t = blockIdx.x; t < NTILES; t += NCTA) {
        const int base = t * BM;
        const int tn   = t + NCTA;

        // ---- layer 0: gates = x @ W0^T -> h0 smem ----
        {
            float acc[2][3][4][4];
#pragma unroll
            for (int mt = 0; mt < 2; mt++)
#pragma unroll
                for (int g = 0; g < 3; g++)
#pragma unroll
                    for (int jt = 0; jt < 4; jt++)
#pragma unroll
                        for (int e = 0; e < 4; e++) acc[mt][g][jt][e] = 0.f;

#pragma unroll 2
            for (int ks = 0; ks < 4; ks++) {
                uint32_t a[2][4];
#pragma unroll
                for (int mt = 0; mt < 2; mt++) {
                    uint32_t addr = sb + SM_X +
                        (uint32_t)(((mg * 32 + mt * 16 + rA) * XSTR + ks * 16 + kA) * 2);
                    ldsm4(a[mt][0], a[mt][1], a[mt][2], a[mt][3], addr);
                }
#pragma unroll
                for (int g = 0; g < 3; g++) {
#pragma unroll
                    for (int jp = 0; jp < 2; jp++) {
                        int jb = jqw * 32 + jp * 16;
                        uint32_t addr = sb + SM_W0 +
                            (uint32_t)(((g * 128 + jb + rB) * W0STR + ks * 16 + kB) * 2);
                        uint32_t b0, b1, b2, b3;
                        ldsm4(b0, b1, b2, b3, addr);
#pragma unroll
                        for (int mt = 0; mt < 2; mt++) {
                            mma16816(acc[mt][g][2 * jp],     a[mt], b0, b1);
                            mma16816(acc[mt][g][2 * jp + 1], a[mt], b2, b3);
                        }
                    }
                }
            }
#pragma unroll
            for (int mt = 0; mt < 2; mt++) {
#pragma unroll
                for (int jt = 0; jt < 4; jt++) {
                    int j0 = jqw * 32 + jt * 8 + qc;
                    float2 bi = *reinterpret_cast<const float2*>(b0_s + j0);
                    float2 bg = *reinterpret_cast<const float2*>(b0_s + 128 + j0);
                    float2 bo = *reinterpret_cast<const float2*>(b0_s + 256 + j0);
                    float v0 = hcell(acc[mt][0][jt][0] + bi.x, acc[mt][1][jt][0] + bg.x,
                                     acc[mt][2][jt][0] + bo.x);
                    float v1 = hcell(acc[mt][0][jt][1] + bi.y, acc[mt][1][jt][1] + bg.y,
                                     acc[mt][2][jt][1] + bo.y);
                    float v2 = hcell(acc[mt][0][jt][2] + bi.x, acc[mt][1][jt][2] + bg.x,
                                     acc[mt][2][jt][2] + bo.x);
                    float v3 = hcell(acc[mt][0][jt][3] + bi.y, acc[mt][1][jt][3] + bg.y,
                                     acc[mt][2][jt][3] + bo.y);
                    int ra = mg * 32 + mt * 16 + qr;
                    *reinterpret_cast<uint32_t*>(smem + SM_H0 + (ra * HSTR + j0) * 2)
                        = h2u(v0, v1);
                    *reinterpret_cast<uint32_t*>(smem + SM_H0 + ((ra + 8) * HSTR + j0) * 2)
                        = h2u(v2, v3);
                }
            }
        }
        __syncthreads();       // X fully read, H0 complete

        // ---- prefetch next tile's x into X buffer (overlaps layer1+heads) ----
        if (tn < NTILES) {
            stage_x(sb, tn, tid);
            cp_commit();
        }
        cp_wait<1>();          // first tile: ensures group B (W1+WH); later: no-op
        __syncthreads();

        // ---- layer 1 + h1 as in-register A-frags ----
        uint32_t hfrag[2][2][4];   // [mt][kt-in-quarter][4]
        {
            float acc[2][3][4][4];
#pragma unroll
            for (int mt = 0; mt < 2; mt++)
#pragma unroll
                for (int g = 0; g < 3; g++)
#pragma unroll
                    for (int jt = 0; jt < 4; jt++)
#pragma unroll
                        for (int e = 0; e < 4; e++) acc[mt][g][jt][e] = 0.f;

#pragma unroll 2
            for (int ks = 0; ks < 8; ks++) {
                uint32_t a[2][4];
#pragma unroll
                for (int mt = 0; mt < 2; mt++) {
                    uint32_t addr = sb + SM_H0 +
                        (uint32_t)(((mg * 32 + mt * 16 + rA) * HSTR + ks * 16 + kA) * 2);
                    ldsm4(a[mt][0], a[mt][1], a[mt][2], a[mt][3], addr);
                }
#pragma unroll
                for (int g = 0; g < 3; g++) {
#pragma unroll
                    for (int jp = 0; jp < 2; jp++) {
                        int jb = jqw * 32 + jp * 16;
                        uint32_t addr = sb + SM_W1 +
                            (uint32_t)(((g * 128 + jb + rB) * W1STR + ks * 16 + kB) * 2);
                        uint32_t b0, b1, b2, b3;
                        ldsm4(b0, b1, b2, b3, addr);
#pragma unroll
                        for (int mt = 0; mt < 2; mt++) {
                            mma16816(acc[mt][g][2 * jp],     a[mt], b0, b1);
                            mma16816(acc[mt][g][2 * jp + 1], a[mt], b2, b3);
                        }
                    }
                }
            }
            // epilogue: hcell -> packed A-fragments (kt = jp)
#pragma unroll
            for (int mt = 0; mt < 2; mt++) {
#pragma unroll
                for (int jp = 0; jp < 2; jp++) {
                    float v[2][4];
#pragma unroll
                    for (int half = 0; half < 2; half++) {
                        int jt = 2 * jp + half;
                        int j0 = jqw * 32 + jt * 8 + qc;
                        float2 bi = *reinterpret_cast<const float2*>(b1_s + j0);
                        float2 bg = *reinterpret_cast<const float2*>(b1_s + 128 + j0);
                        float2 bo = *reinterpret_cast<const float2*>(b1_s + 256 + j0);
                        v[half][0] = hcell(acc[mt][0][jt][0] + bi.x, acc[mt][1][jt][0] + bg.x,
                                           acc[mt][2][jt][0] + bo.x);
                        v[half][1] = hcell(acc[mt][0][jt][1] + bi.y, acc[mt][1][jt][1] + bg.y,
                                           acc[mt][2][jt][1] + bo.y);
                        v[half][2] = hcell(acc[mt][0][jt][2] + bi.x, acc[mt][1][jt][2] + bg.x,
                                           acc[mt][2][jt][2] + bo.x);
                        v[half][3] = hcell(acc[mt][0][jt][3] + bi.y, acc[mt][1][jt][3] + bg.y,
                                           acc[mt][2][jt][3] + bo.y);
                    }
                    hfrag[mt][jp][0] = h2u(v[0][0], v[0][1]);
                    hfrag[mt][jp][1] = h2u(v[0][2], v[0][3]);
                    hfrag[mt][jp][2] = h2u(v[1][0], v[1][1]);
                    hfrag[mt][jp][3] = h2u(v[1][2], v[1][3]);
                }
            }
        }

        // ---- heads: partial [m x 17] over this warp's 32-k chunk ----
        float hacc[2][3][4];
#pragma unroll
        for (int mt = 0; mt < 2; mt++)
#pragma unroll
            for (int nt = 0; nt < 3; nt++)
#pragma unroll
                for (int e = 0; e < 4; e++) hacc[mt][nt][e] = 0.f;

#pragma unroll
        for (int kt = 0; kt < 2; kt++) {
            int kg = jqw * 32 + kt * 16;
            uint32_t b0, b1, b2, b3, c0, c1;
            uint32_t addr01 = sb + SM_WH + (uint32_t)(((rB) * WHSTR + kg + kB) * 2);
            ldsm4(b0, b1, b2, b3, addr01);
            uint32_t addr2 = sb + SM_WH +
                (uint32_t)(((16 + (lane & 7)) * WHSTR + kg + ((lane >> 3) & 1) * 8) * 2);
            ldsm2(c0, c1, addr2);
#pragma unroll
            for (int mt = 0; mt < 2; mt++) {
                mma16816(hacc[mt][0], hfrag[mt][kt], b0, b1);
                mma16816(hacc[mt][1], hfrag[mt][kt], b2, b3);
                mma16816(hacc[mt][2], hfrag[mt][kt], c0, c1);
            }
        }

        // ---- 4-way cross-warp (j-quarter) reduction (BUF aliases H0) ----
        __syncthreads();       // all H0 reads done -> alias safe
        float* buf = reinterpret_cast<float*>(smem + SM_BUF);
#pragma unroll
        for (int mt = 0; mt < 2; mt++)
#pragma unroll
            for (int nt = 0; nt < 3; nt++)
#pragma unroll
                for (int e = 0; e < 4; e++) {
                    int n = nt * 8 + qc + (e & 1);
                    if (n < 17) {
                        int m = mg * 32 + mt * 16 + qr + ((e >= 2) ? 8 : 0);
                        buf[(jqw * BM + m) * BUFSTR + n] = hacc[mt][nt][e];
                    }
                }
        __syncthreads();

        if (tid < 2 * BM) {
            int row = tid >> 1, hn = tid & 1;
            float s[8];
#pragma unroll
            for (int c = 0; c < 8; c++) s[c] = bp_s[hn * 8 + c];
#pragma unroll
            for (int q = 0; q < 4; q++) {
                const float* src = buf + (q * BM + row) * BUFSTR + hn * 8;
#pragma unroll
                for (int c = 0; c < 8; c++) s[c] += src[c];
            }
            float4* dst = reinterpret_cast<float4*>(
                out_policy + (size_t)(base + row) * NUM_ACT + hn * 8);
            dst[0] = make_float4(s[0], s[1], s[2], s[3]);
            dst[1] = make_float4(s[4], s[5], s[6], s[7]);
        } else if (tid < 3 * BM) {
            int row = tid - 2 * BM;
            float v = bv_s[0];
#pragma unroll
            for (int q = 0; q < 4; q++) v += buf[(q * BM + row) * BUFSTR + 16];
            out_value[base + row] = v;
        }

        if (tn < NTILES) {
            cp_wait<0>();      // next x tile resident
            __syncthreads();   // visibility of other threads' copies + BUF->H0 reuse
        }
    }
}

extern "C" void kernel_launch(void* const* d_in, const int* in_sizes, int n_in,
                              void* d_out, int out_size)
{
    (void)in_sizes; (void)n_in; (void)out_size;
    // 0:x 1:Wih0 2:Whh0(dead) 3:bih0 4:bhh0 5:Wih1 6:Whh1(dead) 7:bih1 8:bhh1
    // 9:Wp 10:bp 11:Wv 12:bv
    const float* x    = (const float*)d_in[0];
    const float* Wih0 = (const float*)d_in[1];
    const float* bih0 = (const float*)d_in[3];
    const float* bhh0 = (const float*)d_in[4];
    const float* Wih1 = (const float*)d_in[5];
    const float* bih1 = (const float*)d_in[7];
    const float* bhh1 = (const float*)d_in[8];
    const float* Wp   = (const float*)d_in[9];
    const float* bp   = (const float*)d_in[10];
    const float* Wv   = (const float*)d_in[11];
    const float* bv   = (const float*)d_in[12];

    float* out        = (float*)d_out;
    float* out_policy = out;
    float* out_value  = out + (size_t)BATCH_N * NUM_ACT;

    prep_weights<<<512, 256>>>(x, Wih0, Wih1, Wp, Wv,
                               bih0, bhh0, bih1, bhh1, bp, bv);

    cudaFuncSetAttribute((const void*)lstm_policy_mma,
                         cudaFuncAttributeMaxDynamicSharedMemorySize, SM_TOTAL);
    lstm_policy_mma<<<NCTA, TPB, SM_TOTAL>>>(out_policy, out_value);
}